// round 1
// baseline (speedup 1.0000x reference)
#include <cuda_runtime.h>
#include <math.h>

#define DIMN    1024
#define NHEADS  16
#define HD      64
#define HIDDEN  4096
#define BSZ     4
#define SEQ     2048
#define MROWS   (BSZ*SEQ)   // 8192

// ---------------- scratch (device globals; no allocation allowed) ----------
__device__ float g_h  [(size_t)MROWS*DIMN];     // LN output (reused for LN2)
__device__ float g_qkv[(size_t)MROWS*3*DIMN];   // qkv projection
__device__ float g_o  [(size_t)MROWS*DIMN];     // attention output
__device__ float g_x1 [(size_t)MROWS*DIMN];     // x after attn residual
__device__ float g_ffn[(size_t)MROWS*HIDDEN];   // FFN hidden

// ---------------- layernorm -------------------------------------------------
__device__ __forceinline__ float block_sum(float v, float* red) {
    __syncthreads();
    #pragma unroll
    for (int o = 16; o; o >>= 1) v += __shfl_down_sync(0xFFFFFFFFu, v, o);
    int w = threadIdx.x >> 5;
    if ((threadIdx.x & 31) == 0) red[w] = v;
    __syncthreads();
    if (threadIdx.x < 32) {
        v = (threadIdx.x < 8) ? red[threadIdx.x] : 0.f;
        #pragma unroll
        for (int o = 4; o; o >>= 1) v += __shfl_down_sync(0xFFFFFFFFu, v, o);
        if (threadIdx.x == 0) red[0] = v;
    }
    __syncthreads();
    return red[0];
}

__global__ __launch_bounds__(256) void ln_kernel(
    const float* __restrict__ in, const float* __restrict__ g,
    const float* __restrict__ b, float* __restrict__ out)
{
    __shared__ float red[32];
    size_t row = blockIdx.x;
    const float4* xr = reinterpret_cast<const float4*>(in + row * DIMN);
    int t = threadIdx.x;
    float4 v = xr[t];

    float s = v.x + v.y + v.z + v.w;
    float mean = block_sum(s, red) * (1.0f / DIMN);

    float dx = v.x - mean, dy = v.y - mean, dz = v.z - mean, dw = v.w - mean;
    float sq = dx*dx + dy*dy + dz*dz + dw*dw;
    float var = block_sum(sq, red) * (1.0f / DIMN);
    float rs = rsqrtf(var + 1e-5f);

    float4 gg = reinterpret_cast<const float4*>(g)[t];
    float4 bb = reinterpret_cast<const float4*>(b)[t];
    float4 o;
    o.x = dx * rs * gg.x + bb.x;
    o.y = dy * rs * gg.y + bb.y;
    o.z = dz * rs * gg.z + bb.z;
    o.w = dw * rs * gg.w + bb.w;
    reinterpret_cast<float4*>(out + row * DIMN)[t] = o;
}

// ---------------- GEMM: C[M,Nc] = A[M,K] @ W[K,Nc]  (+ epilogue) ------------
// EPI: 0 = plain store, 1 = +bias +residual, 2 = +bias then exact GELU
template<int EPI>
__global__ __launch_bounds__(256) void gemm128(
    const float* __restrict__ A, const float* __restrict__ W,
    const float* __restrict__ bias, const float* __restrict__ res,
    float* __restrict__ C, int K, int Nc)
{
    __shared__ float As[16][128];
    __shared__ float Bs[16][128];

    const int bm = blockIdx.y * 128;
    const int bn = blockIdx.x * 128;
    const int t  = threadIdx.x;
    const int ty = t >> 4;           // 0..15
    const int tx = t & 15;           // 0..15

    float acc[8][8];
    #pragma unroll
    for (int i = 0; i < 8; i++)
        #pragma unroll
        for (int j = 0; j < 8; j++) acc[i][j] = 0.f;

    for (int k0 = 0; k0 < K; k0 += 16) {
        // A tile: 128 rows x 16 cols -> As[k][m] (transposed)
        #pragma unroll
        for (int i = 0; i < 2; i++) {
            int l4 = t + i * 256;                 // 0..511
            int m  = l4 >> 2;
            int kq = l4 & 3;
            float4 a = *reinterpret_cast<const float4*>(
                A + (size_t)(bm + m) * K + k0 + kq * 4);
            As[kq*4+0][m] = a.x; As[kq*4+1][m] = a.y;
            As[kq*4+2][m] = a.z; As[kq*4+3][m] = a.w;
        }
        // B tile: 16 x 128, natural layout
        #pragma unroll
        for (int i = 0; i < 2; i++) {
            int l4 = t + i * 256;                 // 0..511
            int kk = l4 >> 5;
            int n4 = l4 & 31;
            *reinterpret_cast<float4*>(&Bs[kk][n4*4]) =
                *reinterpret_cast<const float4*>(
                    W + (size_t)(k0 + kk) * Nc + bn + n4 * 4);
        }
        __syncthreads();

        #pragma unroll
        for (int kk = 0; kk < 16; kk++) {
            float a[8], b[8];
            *reinterpret_cast<float4*>(a)     = *reinterpret_cast<float4*>(&As[kk][ty*8]);
            *reinterpret_cast<float4*>(a + 4) = *reinterpret_cast<float4*>(&As[kk][ty*8+4]);
            *reinterpret_cast<float4*>(b)     = *reinterpret_cast<float4*>(&Bs[kk][tx*8]);
            *reinterpret_cast<float4*>(b + 4) = *reinterpret_cast<float4*>(&Bs[kk][tx*8+4]);
            #pragma unroll
            for (int i = 0; i < 8; i++)
                #pragma unroll
                for (int j = 0; j < 8; j++)
                    acc[i][j] = fmaf(a[i], b[j], acc[i][j]);
        }
        __syncthreads();
    }

    // epilogue
    #pragma unroll
    for (int i = 0; i < 8; i++) {
        size_t row = bm + ty * 8 + i;
        #pragma unroll
        for (int j4 = 0; j4 < 2; j4++) {
            int col = bn + tx * 8 + j4 * 4;
            float4 r;
            r.x = acc[i][j4*4+0]; r.y = acc[i][j4*4+1];
            r.z = acc[i][j4*4+2]; r.w = acc[i][j4*4+3];
            if (EPI >= 1) {
                float4 bi = *reinterpret_cast<const float4*>(bias + col);
                r.x += bi.x; r.y += bi.y; r.z += bi.z; r.w += bi.w;
            }
            if (EPI == 1) {
                float4 rr = *reinterpret_cast<const float4*>(res + row * Nc + col);
                r.x += rr.x; r.y += rr.y; r.z += rr.z; r.w += rr.w;
            }
            if (EPI == 2) {
                const float k = 0.70710678118654752f;
                r.x = 0.5f * r.x * (1.f + erff(r.x * k));
                r.y = 0.5f * r.y * (1.f + erff(r.y * k));
                r.z = 0.5f * r.z * (1.f + erff(r.z * k));
                r.w = 0.5f * r.w * (1.f + erff(r.w * k));
            }
            *reinterpret_cast<float4*>(C + row * Nc + col) = r;
        }
    }
}

// ---------------- attention (flash-style, 1 thread = 1 query row) ----------
// grid: (B*HEADS, SEQ/128), block: 128 threads
__global__ __launch_bounds__(128) void attn_kernel(
    const float* __restrict__ qkv, float* __restrict__ out)
{
    __shared__ float sK[64 * HD];   // 16 KB
    __shared__ float sV[64 * HD];   // 16 KB

    const int bh = blockIdx.x;                 // 0..63
    const int b  = bh / NHEADS;
    const int h  = bh % NHEADS;
    const int q0 = blockIdx.y * 128;
    const int t  = threadIdx.x;                // query row within tile

    // load my q row (scale folded in)
    const float* qbase = qkv + ((size_t)(b * SEQ + q0 + t) * (3 * DIMN)) + h * HD;
    float4 q[16];
    #pragma unroll
    for (int i = 0; i < 16; i++) {
        q[i] = reinterpret_cast<const float4*>(qbase)[i];
        q[i].x *= 0.125f; q[i].y *= 0.125f; q[i].z *= 0.125f; q[i].w *= 0.125f;
    }

    float m = -1e30f, l = 0.f;
    float4 o[16];
    #pragma unroll
    for (int i = 0; i < 16; i++) o[i] = make_float4(0.f, 0.f, 0.f, 0.f);

    const float4* k4 = reinterpret_cast<const float4*>(sK);
    const float4* v4 = reinterpret_cast<const float4*>(sV);

    for (int kt = 0; kt < SEQ / 64; kt++) {
        __syncthreads();
        // cooperative K/V tile load: 64 rows x 64 floats each = 1024 float4 each
        #pragma unroll
        for (int i = 0; i < 8; i++) {
            int l4i = t + i * 128;               // 0..1023
            int row = l4i >> 4;                  // kv row 0..63
            int c4  = l4i & 15;
            const float* kb = qkv + ((size_t)(b * SEQ + kt * 64 + row) * (3 * DIMN))
                              + DIMN + h * HD;
            reinterpret_cast<float4*>(sK)[row * 16 + c4] =
                reinterpret_cast<const float4*>(kb)[c4];
            reinterpret_cast<float4*>(sV)[row * 16 + c4] =
                reinterpret_cast<const float4*>(kb + DIMN)[c4];
        }
        __syncthreads();

        #pragma unroll 2
        for (int j = 0; j < 64; j++) {
            // s = q . k_j  (4 independent FMA chains)
            float4 acc = make_float4(0.f, 0.f, 0.f, 0.f);
            #pragma unroll
            for (int i = 0; i < 16; i++) {
                float4 kk = k4[j * 16 + i];     // broadcast across lanes
                acc.x = fmaf(q[i].x, kk.x, acc.x);
                acc.y = fmaf(q[i].y, kk.y, acc.y);
                acc.z = fmaf(q[i].z, kk.z, acc.z);
                acc.w = fmaf(q[i].w, kk.w, acc.w);
            }
            float s = (acc.x + acc.y) + (acc.z + acc.w);

            if (s > m) {                         // rare (~ln(N) per row)
                float alpha = __expf(m - s);
                m = s;
                l *= alpha;
                #pragma unroll
                for (int i = 0; i < 16; i++) {
                    o[i].x *= alpha; o[i].y *= alpha;
                    o[i].z *= alpha; o[i].w *= alpha;
                }
            }
            float p = __expf(s - m);
            l += p;
            #pragma unroll
            for (int i = 0; i < 16; i++) {
                float4 vv = v4[j * 16 + i];     // broadcast
                o[i].x = fmaf(p, vv.x, o[i].x);
                o[i].y = fmaf(p, vv.y, o[i].y);
                o[i].z = fmaf(p, vv.z, o[i].z);
                o[i].w = fmaf(p, vv.w, o[i].w);
            }
        }
    }

    float inv = 1.0f / l;
    float* ob = out + ((size_t)(b * SEQ + q0 + t) * DIMN) + h * HD;
    #pragma unroll
    for (int i = 0; i < 16; i++) {
        float4 r = make_float4(o[i].x * inv, o[i].y * inv, o[i].z * inv, o[i].w * inv);
        reinterpret_cast<float4*>(ob)[i] = r;
    }
}

// ---------------- launch ----------------------------------------------------
extern "C" void kernel_launch(void* const* d_in, const int* in_sizes, int n_in,
                              void* d_out, int out_size)
{
    (void)in_sizes; (void)n_in; (void)out_size;
    const float* x      = (const float*)d_in[0];
    const float* w_qkv  = (const float*)d_in[1];
    const float* w_proj = (const float*)d_in[2];
    const float* b_proj = (const float*)d_in[3];
    const float* ln1_g  = (const float*)d_in[4];
    const float* ln1_b  = (const float*)d_in[5];
    const float* w1     = (const float*)d_in[6];
    const float* b1     = (const float*)d_in[7];
    const float* w2     = (const float*)d_in[8];
    const float* b2     = (const float*)d_in[9];
    const float* ln2_g  = (const float*)d_in[10];
    const float* ln2_b  = (const float*)d_in[11];
    float* out = (float*)d_out;

    float *p_h, *p_qkv, *p_o, *p_x1, *p_ffn;
    cudaGetSymbolAddress((void**)&p_h,   g_h);
    cudaGetSymbolAddress((void**)&p_qkv, g_qkv);
    cudaGetSymbolAddress((void**)&p_o,   g_o);
    cudaGetSymbolAddress((void**)&p_x1,  g_x1);
    cudaGetSymbolAddress((void**)&p_ffn, g_ffn);

    // 1) LN1
    ln_kernel<<<MROWS, 256>>>(x, ln1_g, ln1_b, p_h);
    // 2) QKV projection: [8192,1024] @ [1024,3072]
    gemm128<0><<<dim3(3*DIMN/128, MROWS/128), 256>>>(p_h, w_qkv, nullptr, nullptr, p_qkv, DIMN, 3*DIMN);
    // 3) attention
    attn_kernel<<<dim3(BSZ*NHEADS, SEQ/128), 128>>>(p_qkv, p_o);
    // 4) output projection + bias + residual
    gemm128<1><<<dim3(DIMN/128, MROWS/128), 256>>>(p_o, w_proj, b_proj, x, p_x1, DIMN, DIMN);
    // 5) LN2
    ln_kernel<<<MROWS, 256>>>(p_x1, ln2_g, ln2_b, p_h);
    // 6) FFN up + GELU
    gemm128<2><<<dim3(HIDDEN/128, MROWS/128), 256>>>(p_h, w1, b1, nullptr, p_ffn, DIMN, HIDDEN);
    // 7) FFN down + bias + residual -> out
    gemm128<1><<<dim3(DIMN/128, MROWS/128), 256>>>(p_ffn, w2, b2, p_x1, out, HIDDEN, DIMN);
}

// round 3
// speedup vs baseline: 2.4665x; 2.4665x over previous
#include <cuda_runtime.h>
#include <math.h>
#include <stdint.h>

#define DIMN    1024
#define NHEADS  16
#define HD      64
#define HIDDEN  4096
#define BSZ     4
#define SEQ     2048
#define MROWS   (BSZ*SEQ)   // 8192

// ---------------- scratch (device globals; no allocation allowed) ----------
__device__ float g_h   [(size_t)MROWS*DIMN];
__device__ float g_qkv [(size_t)MROWS*3*DIMN];
__device__ float g_o   [(size_t)MROWS*DIMN];
__device__ float g_x1  [(size_t)MROWS*DIMN];
__device__ float g_ffn [(size_t)MROWS*HIDDEN];

// ---------------- helpers ----------------------------------------------------
__device__ __forceinline__ float to_tf32(float x) {
    float r;
    asm("cvt.rna.tf32.f32 %0, %1;" : "=f"(r) : "f"(x));
    return r;
}
__device__ __forceinline__ float4 cvt4(float4 v) {
    v.x = to_tf32(v.x); v.y = to_tf32(v.y);
    v.z = to_tf32(v.z); v.w = to_tf32(v.w);
    return v;
}
__device__ __forceinline__ void mma_tf32(float* d, const uint32_t* a, const uint32_t* b) {
    asm volatile(
        "mma.sync.aligned.m16n8k8.row.col.f32.tf32.tf32.f32 "
        "{%0,%1,%2,%3}, {%4,%5,%6,%7}, {%8,%9}, {%0,%1,%2,%3};"
        : "+f"(d[0]), "+f"(d[1]), "+f"(d[2]), "+f"(d[3])
        : "r"(a[0]), "r"(a[1]), "r"(a[2]), "r"(a[3]), "r"(b[0]), "r"(b[1]));
}

// ---------------- layernorm -------------------------------------------------
__device__ __forceinline__ float block_sum(float v, float* red) {
    __syncthreads();
    #pragma unroll
    for (int o = 16; o; o >>= 1) v += __shfl_down_sync(0xFFFFFFFFu, v, o);
    int w = threadIdx.x >> 5;
    if ((threadIdx.x & 31) == 0) red[w] = v;
    __syncthreads();
    if (threadIdx.x < 32) {
        v = (threadIdx.x < 8) ? red[threadIdx.x] : 0.f;
        #pragma unroll
        for (int o = 4; o; o >>= 1) v += __shfl_down_sync(0xFFFFFFFFu, v, o);
        if (threadIdx.x == 0) red[0] = v;
    }
    __syncthreads();
    return red[0];
}

__global__ __launch_bounds__(256) void ln_kernel(
    const float* __restrict__ in, const float* __restrict__ g,
    const float* __restrict__ b, float* __restrict__ out)
{
    __shared__ float red[32];
    size_t row = blockIdx.x;
    const float4* xr = reinterpret_cast<const float4*>(in + row * DIMN);
    int t = threadIdx.x;
    float4 v = xr[t];

    float s = v.x + v.y + v.z + v.w;
    float mean = block_sum(s, red) * (1.0f / DIMN);

    float dx = v.x - mean, dy = v.y - mean, dz = v.z - mean, dw = v.w - mean;
    float sq = dx*dx + dy*dy + dz*dz + dw*dw;
    float var = block_sum(sq, red) * (1.0f / DIMN);
    float rs = rsqrtf(var + 1e-5f);

    float4 gg = reinterpret_cast<const float4*>(g)[t];
    float4 bb = reinterpret_cast<const float4*>(b)[t];
    float4 o;
    o.x = dx * rs * gg.x + bb.x;
    o.y = dy * rs * gg.y + bb.y;
    o.z = dz * rs * gg.z + bb.z;
    o.w = dw * rs * gg.w + bb.w;
    reinterpret_cast<float4*>(out + row * DIMN)[t] = o;
}

// ---------------- tf32 tensor-core GEMM (mma.sync m16n8k8) -------------------
// C[M,Nc] = A[M,K] @ W[K,Nc]  (+ epilogue). 256 thr = 8 warps, CTA tile 128x128.
// Warp tile 32x64 = 2 (m16) x 8 (n8). K-chunk 32, double-buffered smem.
// EPI: 0 plain, 1 +bias+residual, 2 +bias+GELU(exact)
#define AS_STRIDE 36     // floats per A row (pad: conflict-free frag loads)
#define BS_STRIDE 132    // floats per B row
#define ASZ (128 * AS_STRIDE)   // 4608 floats
#define BSZ_ (32 * BS_STRIDE)   // 4224 floats
#define GEMM_SMEM ((2 * (ASZ + BSZ_)) * 4)   // 70656 bytes

template<int EPI>
__global__ __launch_bounds__(256, 1) void gemm_tc(
    const float* __restrict__ A, const float* __restrict__ W,
    const float* __restrict__ bias, const float* __restrict__ res,
    float* __restrict__ C, int K, int Nc)
{
    extern __shared__ float sm[];
    float* AsBase = sm;                 // 2 x ASZ
    float* BsBase = sm + 2 * ASZ;       // 2 x BSZ_

    const int t    = threadIdx.x;
    const int lane = t & 31;
    const int wid  = t >> 5;
    const int wm   = wid & 3;           // warp row 0..3 (32 rows each)
    const int wn   = wid >> 2;          // warp col 0..1 (64 cols each)
    const int bm   = blockIdx.y * 128;
    const int bn   = blockIdx.x * 128;
    const int NC   = K >> 5;            // K/32 chunks

    float acc[2][8][4];
    #pragma unroll
    for (int mt = 0; mt < 2; mt++)
        #pragma unroll
        for (int nt = 0; nt < 8; nt++)
            #pragma unroll
            for (int i = 0; i < 4; i++) acc[mt][nt][i] = 0.f;

    // per-thread gmem->smem coordinates
    const int am = t >> 1;                 // A row handled (2 float4 per row)... 
    // A: idx = t + i*256, m = idx>>3, kq = idx&7  (128 rows x 8 float4)
    // B: idx = t + i*256, kk = idx>>5, n4 = idx&31 (32 rows x 32 float4)
    (void)am;

    float4 ar[4], br[4];

    // ---- prologue: load chunk 0 into buffer 0
    #pragma unroll
    for (int i = 0; i < 4; i++) {
        int idx = t + i * 256;
        int m = idx >> 3, kq = idx & 7;
        ar[i] = cvt4(*reinterpret_cast<const float4*>(A + (size_t)(bm + m) * K + kq * 4));
        int kk = idx >> 5, n4 = idx & 31;
        br[i] = cvt4(*reinterpret_cast<const float4*>(W + (size_t)kk * Nc + bn + n4 * 4));
    }
    #pragma unroll
    for (int i = 0; i < 4; i++) {
        int idx = t + i * 256;
        int m = idx >> 3, kq = idx & 7;
        *reinterpret_cast<float4*>(AsBase + m * AS_STRIDE + kq * 4) = ar[i];
        int kk = idx >> 5, n4 = idx & 31;
        *reinterpret_cast<float4*>(BsBase + kk * BS_STRIDE + n4 * 4) = br[i];
    }
    __syncthreads();

    for (int c = 0; c < NC; c++) {
        const int buf = c & 1;
        const float* As = AsBase + buf * ASZ;
        const float* Bs = BsBase + buf * BSZ_;

        // ---- issue LDGs for next chunk (latency hidden behind MMAs)
        if (c + 1 < NC) {
            int k0 = (c + 1) << 5;
            #pragma unroll
            for (int i = 0; i < 4; i++) {
                int idx = t + i * 256;
                int m = idx >> 3, kq = idx & 7;
                ar[i] = cvt4(*reinterpret_cast<const float4*>(
                    A + (size_t)(bm + m) * K + k0 + kq * 4));
                int kk = idx >> 5, n4 = idx & 31;
                br[i] = cvt4(*reinterpret_cast<const float4*>(
                    W + (size_t)(k0 + kk) * Nc + bn + n4 * 4));
            }
        }

        // ---- compute: 4 k-steps of 8
        #pragma unroll
        for (int ks = 0; ks < 4; ks++) {
            const int krow = ks * 8 + (lane & 3);
            uint32_t af[2][4], bf[8][2];
            #pragma unroll
            for (int mt = 0; mt < 2; mt++) {
                int r = wm * 32 + mt * 16 + (lane >> 2);
                af[mt][0] = __float_as_uint(As[(r    ) * AS_STRIDE + krow    ]);
                af[mt][1] = __float_as_uint(As[(r + 8) * AS_STRIDE + krow    ]);
                af[mt][2] = __float_as_uint(As[(r    ) * AS_STRIDE + krow + 4]);
                af[mt][3] = __float_as_uint(As[(r + 8) * AS_STRIDE + krow + 4]);
            }
            #pragma unroll
            for (int nt = 0; nt < 8; nt++) {
                int cn = wn * 64 + nt * 8 + (lane >> 2);
                bf[nt][0] = __float_as_uint(Bs[(krow    ) * BS_STRIDE + cn]);
                bf[nt][1] = __float_as_uint(Bs[(krow + 4) * BS_STRIDE + cn]);
            }
            #pragma unroll
            for (int mt = 0; mt < 2; mt++)
                #pragma unroll
                for (int nt = 0; nt < 8; nt++)
                    mma_tf32(acc[mt][nt], af[mt], bf[nt]);
        }

        // ---- store next chunk into other buffer
        if (c + 1 < NC) {
            float* Asn = AsBase + (buf ^ 1) * ASZ;
            float* Bsn = BsBase + (buf ^ 1) * BSZ_;
            #pragma unroll
            for (int i = 0; i < 4; i++) {
                int idx = t + i * 256;
                int m = idx >> 3, kq = idx & 7;
                *reinterpret_cast<float4*>(Asn + m * AS_STRIDE + kq * 4) = ar[i];
                int kk = idx >> 5, n4 = idx & 31;
                *reinterpret_cast<float4*>(Bsn + kk * BS_STRIDE + n4 * 4) = br[i];
            }
        }
        __syncthreads();
    }

    // ---- epilogue
    #pragma unroll
    for (int mt = 0; mt < 2; mt++) {
        #pragma unroll
        for (int half = 0; half < 2; half++) {
            size_t row = (size_t)bm + wm * 32 + mt * 16 + (lane >> 2) + half * 8;
            #pragma unroll
            for (int nt = 0; nt < 8; nt++) {
                int col = bn + wn * 64 + nt * 8 + 2 * (lane & 3);
                float vx = acc[mt][nt][half * 2 + 0];
                float vy = acc[mt][nt][half * 2 + 1];
                if (EPI >= 1) {
                    vx += bias[col];
                    vy += bias[col + 1];
                }
                if (EPI == 1) {
                    const float2 rr = *reinterpret_cast<const float2*>(res + row * Nc + col);
                    vx += rr.x; vy += rr.y;
                }
                if (EPI == 2) {
                    const float kk = 0.70710678118654752f;
                    vx = 0.5f * vx * (1.f + erff(vx * kk));
                    vy = 0.5f * vy * (1.f + erff(vy * kk));
                }
                float2 o; o.x = vx; o.y = vy;
                *reinterpret_cast<float2*>(C + row * Nc + col) = o;
            }
        }
    }
}

// ---------------- attention (flash-style, 1 thread = 1 query row) ----------
__global__ __launch_bounds__(128) void attn_kernel(
    const float* __restrict__ qkv, float* __restrict__ out)
{
    __shared__ float sK[64 * HD];
    __shared__ float sV[64 * HD];

    const int bh = blockIdx.x;
    const int b  = bh / NHEADS;
    const int h  = bh % NHEADS;
    const int q0 = blockIdx.y * 128;
    const int t  = threadIdx.x;

    const float* qbase = qkv + ((size_t)(b * SEQ + q0 + t) * (3 * DIMN)) + h * HD;
    float4 q[16];
    #pragma unroll
    for (int i = 0; i < 16; i++) {
        q[i] = reinterpret_cast<const float4*>(qbase)[i];
        q[i].x *= 0.125f; q[i].y *= 0.125f; q[i].z *= 0.125f; q[i].w *= 0.125f;
    }

    float m = -1e30f, l = 0.f;
    float4 o[16];
    #pragma unroll
    for (int i = 0; i < 16; i++) o[i] = make_float4(0.f, 0.f, 0.f, 0.f);

    const float4* k4 = reinterpret_cast<const float4*>(sK);
    const float4* v4 = reinterpret_cast<const float4*>(sV);

    for (int kt = 0; kt < SEQ / 64; kt++) {
        __syncthreads();
        #pragma unroll
        for (int i = 0; i < 8; i++) {
            int l4i = t + i * 128;
            int row = l4i >> 4;
            int c4  = l4i & 15;
            const float* kb = qkv + ((size_t)(b * SEQ + kt * 64 + row) * (3 * DIMN))
                              + DIMN + h * HD;
            reinterpret_cast<float4*>(sK)[row * 16 + c4] =
                reinterpret_cast<const float4*>(kb)[c4];
            reinterpret_cast<float4*>(sV)[row * 16 + c4] =
                reinterpret_cast<const float4*>(kb + DIMN)[c4];
        }
        __syncthreads();

        #pragma unroll 2
        for (int j = 0; j < 64; j++) {
            float4 acc = make_float4(0.f, 0.f, 0.f, 0.f);
            #pragma unroll
            for (int i = 0; i < 16; i++) {
                float4 kk = k4[j * 16 + i];
                acc.x = fmaf(q[i].x, kk.x, acc.x);
                acc.y = fmaf(q[i].y, kk.y, acc.y);
                acc.z = fmaf(q[i].z, kk.z, acc.z);
                acc.w = fmaf(q[i].w, kk.w, acc.w);
            }
            float s = (acc.x + acc.y) + (acc.z + acc.w);

            if (s > m) {
                float alpha = __expf(m - s);
                m = s;
                l *= alpha;
                #pragma unroll
                for (int i = 0; i < 16; i++) {
                    o[i].x *= alpha; o[i].y *= alpha;
                    o[i].z *= alpha; o[i].w *= alpha;
                }
            }
            float p = __expf(s - m);
            l += p;
            #pragma unroll
            for (int i = 0; i < 16; i++) {
                float4 vv = v4[j * 16 + i];
                o[i].x = fmaf(p, vv.x, o[i].x);
                o[i].y = fmaf(p, vv.y, o[i].y);
                o[i].z = fmaf(p, vv.z, o[i].z);
                o[i].w = fmaf(p, vv.w, o[i].w);
            }
        }
    }

    float inv = 1.0f / l;
    float* ob = out + ((size_t)(b * SEQ + q0 + t) * DIMN) + h * HD;
    #pragma unroll
    for (int i = 0; i < 16; i++) {
        float4 r = make_float4(o[i].x * inv, o[i].y * inv, o[i].z * inv, o[i].w * inv);
        reinterpret_cast<float4*>(ob)[i] = r;
    }
}

// ---------------- launch ----------------------------------------------------
extern "C" void kernel_launch(void* const* d_in, const int* in_sizes, int n_in,
                              void* d_out, int out_size)
{
    (void)in_sizes; (void)n_in; (void)out_size;
    const float* x      = (const float*)d_in[0];
    const float* w_qkv  = (const float*)d_in[1];
    const float* w_proj = (const float*)d_in[2];
    const float* b_proj = (const float*)d_in[3];
    const float* ln1_g  = (const float*)d_in[4];
    const float* ln1_b  = (const float*)d_in[5];
    const float* w1     = (const float*)d_in[6];
    const float* b1     = (const float*)d_in[7];
    const float* w2     = (const float*)d_in[8];
    const float* b2     = (const float*)d_in[9];
    const float* ln2_g  = (const float*)d_in[10];
    const float* ln2_b  = (const float*)d_in[11];
    float* out = (float*)d_out;

    float *p_h, *p_qkv, *p_o, *p_x1, *p_ffn;
    cudaGetSymbolAddress((void**)&p_h,   g_h);
    cudaGetSymbolAddress((void**)&p_qkv, g_qkv);
    cudaGetSymbolAddress((void**)&p_o,   g_o);
    cudaGetSymbolAddress((void**)&p_x1,  g_x1);
    cudaGetSymbolAddress((void**)&p_ffn, g_ffn);

    cudaFuncSetAttribute(gemm_tc<0>, cudaFuncAttributeMaxDynamicSharedMemorySize, GEMM_SMEM);
    cudaFuncSetAttribute(gemm_tc<1>, cudaFuncAttributeMaxDynamicSharedMemorySize, GEMM_SMEM);
    cudaFuncSetAttribute(gemm_tc<2>, cudaFuncAttributeMaxDynamicSharedMemorySize, GEMM_SMEM);

    // 1) LN1
    ln_kernel<<<MROWS, 256>>>(x, ln1_g, ln1_b, p_h);
    // 2) QKV projection: [8192,1024] @ [1024,3072]
    gemm_tc<0><<<dim3(3*DIMN/128, MROWS/128), 256, GEMM_SMEM>>>(p_h, w_qkv, nullptr, nullptr, p_qkv, DIMN, 3*DIMN);
    // 3) attention
    attn_kernel<<<dim3(BSZ*NHEADS, SEQ/128), 128>>>(p_qkv, p_o);
    // 4) output projection + bias + residual
    gemm_tc<1><<<dim3(DIMN/128, MROWS/128), 256, GEMM_SMEM>>>(p_o, w_proj, b_proj, x, p_x1, DIMN, DIMN);
    // 5) LN2
    ln_kernel<<<MROWS, 256>>>(p_x1, ln2_g, ln2_b, p_h);
    // 6) FFN up + GELU
    gemm_tc<2><<<dim3(HIDDEN/128, MROWS/128), 256, GEMM_SMEM>>>(p_h, w1, b1, nullptr, p_ffn, DIMN, HIDDEN);
    // 7) FFN down + bias + residual -> out
    gemm_tc<1><<<dim3(DIMN/128, MROWS/128), 256, GEMM_SMEM>>>(p_ffn, w2, b2, p_x1, out, HIDDEN, DIMN);
}

// round 4
// speedup vs baseline: 4.1771x; 1.6936x over previous
#include <cuda_runtime.h>
#include <math.h>
#include <stdint.h>

#define DIMN    1024
#define NHEADS  16
#define HD      64
#define HIDDEN  4096
#define BB      4
#define SEQ     2048
#define MROWS   (BB*SEQ)   // 8192

// ---------------- scratch (device globals; no allocation allowed) ----------
__device__ float g_h   [(size_t)MROWS*DIMN];
__device__ float g_qkv [(size_t)MROWS*3*DIMN];
__device__ float g_o   [(size_t)MROWS*DIMN];
__device__ float g_x1  [(size_t)MROWS*DIMN];
__device__ float g_ffn [(size_t)MROWS*HIDDEN];

// ---------------- helpers ----------------------------------------------------
__device__ __forceinline__ float to_tf32(float x) {
    float r;
    asm("cvt.rna.tf32.f32 %0, %1;" : "=f"(r) : "f"(x));
    return r;
}
__device__ __forceinline__ float4 cvt4(float4 v) {
    v.x = to_tf32(v.x); v.y = to_tf32(v.y);
    v.z = to_tf32(v.z); v.w = to_tf32(v.w);
    return v;
}
__device__ __forceinline__ void mma_tf32(float* d, const uint32_t* a, const uint32_t* b) {
    asm volatile(
        "mma.sync.aligned.m16n8k8.row.col.f32.tf32.tf32.f32 "
        "{%0,%1,%2,%3}, {%4,%5,%6,%7}, {%8,%9}, {%0,%1,%2,%3};"
        : "+f"(d[0]), "+f"(d[1]), "+f"(d[2]), "+f"(d[3])
        : "r"(a[0]), "r"(a[1]), "r"(a[2]), "r"(a[3]), "r"(b[0]), "r"(b[1]));
}

// ---------------- layernorm -------------------------------------------------
__device__ __forceinline__ float block_sum(float v, float* red) {
    __syncthreads();
    #pragma unroll
    for (int o = 16; o; o >>= 1) v += __shfl_down_sync(0xFFFFFFFFu, v, o);
    int w = threadIdx.x >> 5;
    if ((threadIdx.x & 31) == 0) red[w] = v;
    __syncthreads();
    if (threadIdx.x < 32) {
        v = (threadIdx.x < 8) ? red[threadIdx.x] : 0.f;
        #pragma unroll
        for (int o = 4; o; o >>= 1) v += __shfl_down_sync(0xFFFFFFFFu, v, o);
        if (threadIdx.x == 0) red[0] = v;
    }
    __syncthreads();
    return red[0];
}

__global__ __launch_bounds__(256) void ln_kernel(
    const float* __restrict__ in, const float* __restrict__ g,
    const float* __restrict__ b, float* __restrict__ out)
{
    __shared__ float red[32];
    size_t row = blockIdx.x;
    const float4* xr = reinterpret_cast<const float4*>(in + row * DIMN);
    int t = threadIdx.x;
    float4 v = xr[t];

    float s = v.x + v.y + v.z + v.w;
    float mean = block_sum(s, red) * (1.0f / DIMN);

    float dx = v.x - mean, dy = v.y - mean, dz = v.z - mean, dw = v.w - mean;
    float sq = dx*dx + dy*dy + dz*dz + dw*dw;
    float var = block_sum(sq, red) * (1.0f / DIMN);
    float rs = rsqrtf(var + 1e-5f);

    float4 gg = reinterpret_cast<const float4*>(g)[t];
    float4 bb = reinterpret_cast<const float4*>(b)[t];
    float4 o;
    o.x = dx * rs * gg.x + bb.x;
    o.y = dy * rs * gg.y + bb.y;
    o.z = dz * rs * gg.z + bb.z;
    o.w = dw * rs * gg.w + bb.w;
    reinterpret_cast<float4*>(out + row * DIMN)[t] = o;
}

// ---------------- tf32 tensor-core GEMM (mma.sync m16n8k8) -------------------
// 512 thr = 16 warps, CTA tile 128x128, warp tile 32x32, K-chunk 32, dbl-buffer.
#define AS_STRIDE 36
#define BS_STRIDE 136
#define ASZ (128 * AS_STRIDE)
#define BSZ_ (32 * BS_STRIDE)
#define GEMM_SMEM ((2 * (ASZ + BSZ_)) * 4)

template<int EPI>
__global__ __launch_bounds__(512, 1) void gemm_tc(
    const float* __restrict__ A, const float* __restrict__ W,
    const float* __restrict__ bias, const float* __restrict__ res,
    float* __restrict__ C, int K, int Nc)
{
    extern __shared__ float sm[];
    float* AsBase = sm;
    float* BsBase = sm + 2 * ASZ;

    const int t    = threadIdx.x;
    const int lane = t & 31;
    const int wid  = t >> 5;            // 0..15
    const int wm   = wid & 3;           // warp row (32 rows)
    const int wn   = wid >> 2;          // warp col (32 cols)
    const int bm   = blockIdx.y * 128;
    const int bn   = blockIdx.x * 128;
    const int NC   = K >> 5;

    float acc[2][4][4];
    #pragma unroll
    for (int mt = 0; mt < 2; mt++)
        #pragma unroll
        for (int nt = 0; nt < 4; nt++)
            #pragma unroll
            for (int i = 0; i < 4; i++) acc[mt][nt][i] = 0.f;

    float4 ar[2], br[2];

    // prologue: chunk 0 -> buffer 0
    #pragma unroll
    for (int i = 0; i < 2; i++) {
        int idx = t + i * 512;
        int m = idx >> 3, kq = idx & 7;
        ar[i] = cvt4(*reinterpret_cast<const float4*>(A + (size_t)(bm + m) * K + kq * 4));
        int kk = idx >> 5, n4 = idx & 31;
        br[i] = cvt4(*reinterpret_cast<const float4*>(W + (size_t)kk * Nc + bn + n4 * 4));
    }
    #pragma unroll
    for (int i = 0; i < 2; i++) {
        int idx = t + i * 512;
        int m = idx >> 3, kq = idx & 7;
        *reinterpret_cast<float4*>(AsBase + m * AS_STRIDE + kq * 4) = ar[i];
        int kk = idx >> 5, n4 = idx & 31;
        *reinterpret_cast<float4*>(BsBase + kk * BS_STRIDE + n4 * 4) = br[i];
    }
    __syncthreads();

    for (int c = 0; c < NC; c++) {
        const int buf = c & 1;
        const float* As = AsBase + buf * ASZ;
        const float* Bs = BsBase + buf * BSZ_;

        if (c + 1 < NC) {
            int k0 = (c + 1) << 5;
            #pragma unroll
            for (int i = 0; i < 2; i++) {
                int idx = t + i * 512;
                int m = idx >> 3, kq = idx & 7;
                ar[i] = cvt4(*reinterpret_cast<const float4*>(
                    A + (size_t)(bm + m) * K + k0 + kq * 4));
                int kk = idx >> 5, n4 = idx & 31;
                br[i] = cvt4(*reinterpret_cast<const float4*>(
                    W + (size_t)(k0 + kk) * Nc + bn + n4 * 4));
            }
        }

        #pragma unroll
        for (int ks = 0; ks < 4; ks++) {
            const int krow = ks * 8 + (lane & 3);
            uint32_t af[2][4], bf[4][2];
            #pragma unroll
            for (int mt = 0; mt < 2; mt++) {
                int r = wm * 32 + mt * 16 + (lane >> 2);
                af[mt][0] = __float_as_uint(As[(r    ) * AS_STRIDE + krow    ]);
                af[mt][1] = __float_as_uint(As[(r + 8) * AS_STRIDE + krow    ]);
                af[mt][2] = __float_as_uint(As[(r    ) * AS_STRIDE + krow + 4]);
                af[mt][3] = __float_as_uint(As[(r + 8) * AS_STRIDE + krow + 4]);
            }
            #pragma unroll
            for (int nt = 0; nt < 4; nt++) {
                int cn = wn * 32 + nt * 8 + (lane >> 2);
                bf[nt][0] = __float_as_uint(Bs[(krow    ) * BS_STRIDE + cn]);
                bf[nt][1] = __float_as_uint(Bs[(krow + 4) * BS_STRIDE + cn]);
            }
            #pragma unroll
            for (int mt = 0; mt < 2; mt++)
                #pragma unroll
                for (int nt = 0; nt < 4; nt++)
                    mma_tf32(acc[mt][nt], af[mt], bf[nt]);
        }

        if (c + 1 < NC) {
            float* Asn = AsBase + (buf ^ 1) * ASZ;
            float* Bsn = BsBase + (buf ^ 1) * BSZ_;
            #pragma unroll
            for (int i = 0; i < 2; i++) {
                int idx = t + i * 512;
                int m = idx >> 3, kq = idx & 7;
                *reinterpret_cast<float4*>(Asn + m * AS_STRIDE + kq * 4) = ar[i];
                int kk = idx >> 5, n4 = idx & 31;
                *reinterpret_cast<float4*>(Bsn + kk * BS_STRIDE + n4 * 4) = br[i];
            }
        }
        __syncthreads();
    }

    // epilogue
    #pragma unroll
    for (int mt = 0; mt < 2; mt++) {
        #pragma unroll
        for (int half = 0; half < 2; half++) {
            size_t row = (size_t)bm + wm * 32 + mt * 16 + (lane >> 2) + half * 8;
            #pragma unroll
            for (int nt = 0; nt < 4; nt++) {
                int col = bn + wn * 32 + nt * 8 + 2 * (lane & 3);
                float vx = acc[mt][nt][half * 2 + 0];
                float vy = acc[mt][nt][half * 2 + 1];
                if (EPI >= 1) {
                    vx += bias[col];
                    vy += bias[col + 1];
                }
                if (EPI == 1) {
                    const float2 rr = *reinterpret_cast<const float2*>(res + row * Nc + col);
                    vx += rr.x; vy += rr.y;
                }
                if (EPI == 2) {
                    const float kk = 0.70710678118654752f;
                    vx = 0.5f * vx * (1.f + erff(vx * kk));
                    vy = 0.5f * vy * (1.f + erff(vy * kk));
                }
                float2 o; o.x = vx; o.y = vy;
                *reinterpret_cast<float2*>(C + row * Nc + col) = o;
            }
        }
    }
}

// ---------------- tensor-core flash attention --------------------------------
// CTA: one (b,h), 64 q-rows; 4 warps x 16 rows. Key tiles of 64.
#define AST 68   // smem stride (floats)
#define ATT_SMEM ((2 * 64 * AST + 4 * 16 * AST) * 4)   // K + V + P(4 warps)

__global__ __launch_bounds__(128) void attn_tc(
    const float* __restrict__ qkv, float* __restrict__ out)
{
    extern __shared__ float smf[];
    float* sK = smf;
    float* sV = smf + 64 * AST;
    const int t = threadIdx.x, lane = t & 31, wid = t >> 5;
    float* sP = smf + 2 * 64 * AST + wid * 16 * AST;

    const int bh = blockIdx.x;
    const int b  = bh / NHEADS;
    const int h  = bh % NHEADS;
    const int q0 = blockIdx.y * 64;

    const int qr = lane >> 2;       // quad row 0..7
    const int qc = lane & 3;        // quad col 0..3
    const int r0 = q0 + wid * 16 + qr;

    // Q fragments, scaled + tf32 (register-resident for the whole kernel)
    uint32_t aq[8][4];
    {
        const float* Q0 = qkv + ((size_t)(b * SEQ + r0)) * (3 * DIMN) + h * HD;
        const float* Q8 = Q0 + 8 * (3 * DIMN);
        #pragma unroll
        for (int kc = 0; kc < 8; kc++) {
            int k_ = kc * 8 + qc;
            aq[kc][0] = __float_as_uint(to_tf32(Q0[k_]     * 0.125f));
            aq[kc][1] = __float_as_uint(to_tf32(Q8[k_]     * 0.125f));
            aq[kc][2] = __float_as_uint(to_tf32(Q0[k_ + 4] * 0.125f));
            aq[kc][3] = __float_as_uint(to_tf32(Q8[k_ + 4] * 0.125f));
        }
    }

    float m0 = -1e30f, m1 = -1e30f, l0 = 0.f, l1 = 0.f;
    float o[8][4];
    #pragma unroll
    for (int nt = 0; nt < 8; nt++)
        #pragma unroll
        for (int i = 0; i < 4; i++) o[nt][i] = 0.f;

    for (int kt = 0; kt < SEQ / 64; kt++) {
        __syncthreads();
        // cooperative K/V tile load (tf32-converted)
        #pragma unroll
        for (int i = 0; i < 8; i++) {
            int idx = t + i * 128;
            int row = idx >> 4, c4 = idx & 15;
            const float* kb = qkv + ((size_t)(b * SEQ + kt * 64 + row)) * (3 * DIMN)
                              + DIMN + h * HD;
            *reinterpret_cast<float4*>(sK + row * AST + c4 * 4) =
                cvt4(*reinterpret_cast<const float4*>(kb + c4 * 4));
            *reinterpret_cast<float4*>(sV + row * AST + c4 * 4) =
                cvt4(*reinterpret_cast<const float4*>(kb + DIMN + c4 * 4));
        }
        __syncthreads();

        // S = Q K^T   (16 x 64 per warp)
        float s[8][4];
        #pragma unroll
        for (int nt = 0; nt < 8; nt++)
            #pragma unroll
            for (int i = 0; i < 4; i++) s[nt][i] = 0.f;
        #pragma unroll
        for (int kc = 0; kc < 8; kc++) {
            #pragma unroll
            for (int nt = 0; nt < 8; nt++) {
                uint32_t bk[2];
                const float* kp = sK + (nt * 8 + qr) * AST + kc * 8 + qc;
                bk[0] = __float_as_uint(kp[0]);
                bk[1] = __float_as_uint(kp[4]);
                mma_tf32(s[nt], aq[kc], bk);
            }
        }

        // online softmax (rows r0: c0/c1, r0+8: c2/c3)
        float mx0 = -1e30f, mx1 = -1e30f;
        #pragma unroll
        for (int nt = 0; nt < 8; nt++) {
            mx0 = fmaxf(mx0, fmaxf(s[nt][0], s[nt][1]));
            mx1 = fmaxf(mx1, fmaxf(s[nt][2], s[nt][3]));
        }
        mx0 = fmaxf(mx0, __shfl_xor_sync(0xFFFFFFFFu, mx0, 1));
        mx0 = fmaxf(mx0, __shfl_xor_sync(0xFFFFFFFFu, mx0, 2));
        mx1 = fmaxf(mx1, __shfl_xor_sync(0xFFFFFFFFu, mx1, 1));
        mx1 = fmaxf(mx1, __shfl_xor_sync(0xFFFFFFFFu, mx1, 2));

        float mn0 = fmaxf(m0, mx0), mn1 = fmaxf(m1, mx1);
        float al0 = __expf(m0 - mn0), al1 = __expf(m1 - mn1);
        m0 = mn0; m1 = mn1;

        float sum0 = 0.f, sum1 = 0.f;
        #pragma unroll
        for (int nt = 0; nt < 8; nt++) {
            s[nt][0] = __expf(s[nt][0] - m0);
            s[nt][1] = __expf(s[nt][1] - m0);
            s[nt][2] = __expf(s[nt][2] - m1);
            s[nt][3] = __expf(s[nt][3] - m1);
            sum0 += s[nt][0] + s[nt][1];
            sum1 += s[nt][2] + s[nt][3];
        }
        sum0 += __shfl_xor_sync(0xFFFFFFFFu, sum0, 1);
        sum0 += __shfl_xor_sync(0xFFFFFFFFu, sum0, 2);
        sum1 += __shfl_xor_sync(0xFFFFFFFFu, sum1, 1);
        sum1 += __shfl_xor_sync(0xFFFFFFFFu, sum1, 2);
        l0 = l0 * al0 + sum0;
        l1 = l1 * al1 + sum1;

        #pragma unroll
        for (int nt = 0; nt < 8; nt++) {
            o[nt][0] *= al0; o[nt][1] *= al0;
            o[nt][2] *= al1; o[nt][3] *= al1;
        }

        // P -> smem (tf32)
        #pragma unroll
        for (int nt = 0; nt < 8; nt++) {
            float2 p01, p23;
            p01.x = to_tf32(s[nt][0]); p01.y = to_tf32(s[nt][1]);
            p23.x = to_tf32(s[nt][2]); p23.y = to_tf32(s[nt][3]);
            *reinterpret_cast<float2*>(sP + qr * AST + nt * 8 + 2 * qc) = p01;
            *reinterpret_cast<float2*>(sP + (qr + 8) * AST + nt * 8 + 2 * qc) = p23;
        }
        __syncwarp();

        // O += P V
        #pragma unroll
        for (int kc = 0; kc < 8; kc++) {
            uint32_t ap[4];
            ap[0] = __float_as_uint(sP[(qr    ) * AST + kc * 8 + qc    ]);
            ap[1] = __float_as_uint(sP[(qr + 8) * AST + kc * 8 + qc    ]);
            ap[2] = __float_as_uint(sP[(qr    ) * AST + kc * 8 + qc + 4]);
            ap[3] = __float_as_uint(sP[(qr + 8) * AST + kc * 8 + qc + 4]);
            #pragma unroll
            for (int nt = 0; nt < 8; nt++) {
                uint32_t bv[2];
                bv[0] = __float_as_uint(sV[(kc * 8 + qc    ) * AST + nt * 8 + qr]);
                bv[1] = __float_as_uint(sV[(kc * 8 + qc + 4) * AST + nt * 8 + qr]);
                mma_tf32(o[nt], ap, bv);
            }
        }
        __syncwarp();
    }

    // normalize + store
    float inv0 = 1.0f / l0, inv1 = 1.0f / l1;
    float* O0 = out + ((size_t)(b * SEQ + r0)) * DIMN + h * HD;
    float* O8 = O0 + 8 * DIMN;
    #pragma unroll
    for (int nt = 0; nt < 8; nt++) {
        int col = nt * 8 + 2 * qc;
        float2 r01, r23;
        r01.x = o[nt][0] * inv0; r01.y = o[nt][1] * inv0;
        r23.x = o[nt][2] * inv1; r23.y = o[nt][3] * inv1;
        *reinterpret_cast<float2*>(O0 + col) = r01;
        *reinterpret_cast<float2*>(O8 + col) = r23;
    }
}

// ---------------- launch ----------------------------------------------------
extern "C" void kernel_launch(void* const* d_in, const int* in_sizes, int n_in,
                              void* d_out, int out_size)
{
    (void)in_sizes; (void)n_in; (void)out_size;
    const float* x      = (const float*)d_in[0];
    const float* w_qkv  = (const float*)d_in[1];
    const float* w_proj = (const float*)d_in[2];
    const float* b_proj = (const float*)d_in[3];
    const float* ln1_g  = (const float*)d_in[4];
    const float* ln1_b  = (const float*)d_in[5];
    const float* w1     = (const float*)d_in[6];
    const float* b1     = (const float*)d_in[7];
    const float* w2     = (const float*)d_in[8];
    const float* b2     = (const float*)d_in[9];
    const float* ln2_g  = (const float*)d_in[10];
    const float* ln2_b  = (const float*)d_in[11];
    float* out = (float*)d_out;

    float *p_h, *p_qkv, *p_o, *p_x1, *p_ffn;
    cudaGetSymbolAddress((void**)&p_h,   g_h);
    cudaGetSymbolAddress((void**)&p_qkv, g_qkv);
    cudaGetSymbolAddress((void**)&p_o,   g_o);
    cudaGetSymbolAddress((void**)&p_x1,  g_x1);
    cudaGetSymbolAddress((void**)&p_ffn, g_ffn);

    cudaFuncSetAttribute(gemm_tc<0>, cudaFuncAttributeMaxDynamicSharedMemorySize, GEMM_SMEM);
    cudaFuncSetAttribute(gemm_tc<1>, cudaFuncAttributeMaxDynamicSharedMemorySize, GEMM_SMEM);
    cudaFuncSetAttribute(gemm_tc<2>, cudaFuncAttributeMaxDynamicSharedMemorySize, GEMM_SMEM);
    cudaFuncSetAttribute(attn_tc,    cudaFuncAttributeMaxDynamicSharedMemorySize, ATT_SMEM);

    // 1) LN1
    ln_kernel<<<MROWS, 256>>>(x, ln1_g, ln1_b, p_h);
    // 2) QKV projection
    gemm_tc<0><<<dim3(3*DIMN/128, MROWS/128), 512, GEMM_SMEM>>>(p_h, w_qkv, nullptr, nullptr, p_qkv, DIMN, 3*DIMN);
    // 3) attention (tensor-core flash)
    attn_tc<<<dim3(BB*NHEADS, SEQ/64), 128, ATT_SMEM>>>(p_qkv, p_o);
    // 4) output projection + bias + residual
    gemm_tc<1><<<dim3(DIMN/128, MROWS/128), 512, GEMM_SMEM>>>(p_o, w_proj, b_proj, x, p_x1, DIMN, DIMN);
    // 5) LN2
    ln_kernel<<<MROWS, 256>>>(p_x1, ln2_g, ln2_b, p_h);
    // 6) FFN up + GELU
    gemm_tc<2><<<dim3(HIDDEN/128, MROWS/128), 512, GEMM_SMEM>>>(p_h, w1, b1, nullptr, p_ffn, DIMN, HIDDEN);
    // 7) FFN down + bias + residual -> out
    gemm_tc<1><<<dim3(DIMN/128, MROWS/128), 512, GEMM_SMEM>>>(p_ffn, w2, b2, p_x1, out, HIDDEN, DIMN);
}

// round 5
// speedup vs baseline: 5.2156x; 1.2486x over previous
#include <cuda_runtime.h>
#include <math.h>
#include <stdint.h>

#define DIMN    1024
#define NHEADS  16
#define HD      64
#define HIDDEN  4096
#define BB      4
#define SEQ     2048
#define MROWS   (BB*SEQ)   // 8192

// ---------------- scratch (device globals; no allocation allowed) ----------
__device__ float g_h   [(size_t)MROWS*DIMN];
__device__ float g_qkv [(size_t)MROWS*3*DIMN];
__device__ float g_o   [(size_t)MROWS*DIMN];
__device__ float g_x1  [(size_t)MROWS*DIMN];
__device__ float g_ffn [(size_t)MROWS*HIDDEN];
__device__ float g_wq  [(size_t)DIMN*3*DIMN];
__device__ float g_wp  [(size_t)DIMN*DIMN];
__device__ float g_w1c [(size_t)DIMN*HIDDEN];
__device__ float g_w2c [(size_t)DIMN*HIDDEN];

// ---------------- helpers ----------------------------------------------------
__device__ __forceinline__ float to_tf32(float x) {
    float r;
    asm("cvt.rna.tf32.f32 %0, %1;" : "=f"(r) : "f"(x));
    return r;
}
__device__ __forceinline__ float4 cvt4(float4 v) {
    v.x = to_tf32(v.x); v.y = to_tf32(v.y);
    v.z = to_tf32(v.z); v.w = to_tf32(v.w);
    return v;
}
__device__ __forceinline__ uint32_t smem_u32(const void* p) {
    uint32_t a;
    asm("{ .reg .u64 t; cvta.to.shared.u64 t, %1; cvt.u32.u64 %0, t; }"
        : "=r"(a) : "l"(p));
    return a;
}
__device__ __forceinline__ void cp16(uint32_t s, const float* g) {
    asm volatile("cp.async.cg.shared.global [%0], [%1], 16;" :: "r"(s), "l"(g) : "memory");
}
__device__ __forceinline__ void mma_tf32(float* d, const uint32_t* a, const uint32_t* b) {
    asm volatile(
        "mma.sync.aligned.m16n8k8.row.col.f32.tf32.tf32.f32 "
        "{%0,%1,%2,%3}, {%4,%5,%6,%7}, {%8,%9}, {%0,%1,%2,%3};"
        : "+f"(d[0]), "+f"(d[1]), "+f"(d[2]), "+f"(d[3])
        : "r"(a[0]), "r"(a[1]), "r"(a[2]), "r"(a[3]), "r"(b[0]), "r"(b[1]));
}

// ---------------- tf32 cvt copy (weights, one-shot) --------------------------
__global__ __launch_bounds__(256) void cvt_copy(
    const float* __restrict__ in, float* __restrict__ out)
{
    size_t i = ((size_t)blockIdx.x * 256 + threadIdx.x) * 4;
    *reinterpret_cast<float4*>(out + i) =
        cvt4(*reinterpret_cast<const float4*>(in + i));
}

// ---------------- layernorm (emits tf32-rounded output) ---------------------
__device__ __forceinline__ float block_sum(float v, float* red) {
    __syncthreads();
    #pragma unroll
    for (int o = 16; o; o >>= 1) v += __shfl_down_sync(0xFFFFFFFFu, v, o);
    int w = threadIdx.x >> 5;
    if ((threadIdx.x & 31) == 0) red[w] = v;
    __syncthreads();
    if (threadIdx.x < 32) {
        v = (threadIdx.x < 8) ? red[threadIdx.x] : 0.f;
        #pragma unroll
        for (int o = 4; o; o >>= 1) v += __shfl_down_sync(0xFFFFFFFFu, v, o);
        if (threadIdx.x == 0) red[0] = v;
    }
    __syncthreads();
    return red[0];
}

__global__ __launch_bounds__(256) void ln_kernel(
    const float* __restrict__ in, const float* __restrict__ g,
    const float* __restrict__ b, float* __restrict__ out)
{
    __shared__ float red[32];
    size_t row = blockIdx.x;
    const float4* xr = reinterpret_cast<const float4*>(in + row * DIMN);
    int t = threadIdx.x;
    float4 v = xr[t];

    float s = v.x + v.y + v.z + v.w;
    float mean = block_sum(s, red) * (1.0f / DIMN);

    float dx = v.x - mean, dy = v.y - mean, dz = v.z - mean, dw = v.w - mean;
    float sq = dx*dx + dy*dy + dz*dz + dw*dw;
    float var = block_sum(sq, red) * (1.0f / DIMN);
    float rs = rsqrtf(var + 1e-5f);

    float4 gg = reinterpret_cast<const float4*>(g)[t];
    float4 bb = reinterpret_cast<const float4*>(b)[t];
    float4 o;
    o.x = to_tf32(dx * rs * gg.x + bb.x);
    o.y = to_tf32(dy * rs * gg.y + bb.y);
    o.z = to_tf32(dz * rs * gg.z + bb.z);
    o.w = to_tf32(dw * rs * gg.w + bb.w);
    reinterpret_cast<float4*>(out + row * DIMN)[t] = o;
}

// ---------------- tf32 tensor-core GEMM, cp.async 4-stage --------------------
// 512 thr = 16 warps, CTA tile 128x128, warp tile 32x32, K-chunk 32.
// Inputs A and W must be pre-rounded to tf32.
// EPI: 0 plain, 1 +bias+residual, 2 +bias+GELU.  ROUND: tf32-round the store.
#define STAGES   4
#define ASTRIDE  36
#define BSTRIDE  136
#define A_FL     (128 * ASTRIDE)            // 4608 floats
#define B_FL     (32 * BSTRIDE)             // 4352 floats
#define STAGE_FL (A_FL + B_FL)              // 8960 floats
#define GEMM_SMEM (STAGES * STAGE_FL * 4)   // 143360 bytes

template<int EPI, int ROUND>
__global__ __launch_bounds__(512, 1) void gemm_tc(
    const float* __restrict__ A, const float* __restrict__ W,
    const float* __restrict__ bias, const float* __restrict__ res,
    float* __restrict__ C, int K, int Nc)
{
    extern __shared__ float sm[];
    const uint32_t smb = smem_u32(sm);

    const int t    = threadIdx.x;
    const int lane = t & 31;
    const int wid  = t >> 5;
    const int wm   = wid & 3;
    const int wn   = wid >> 2;
    const int bm   = blockIdx.y * 128;
    const int bn   = blockIdx.x * 128;
    const int NC   = K >> 5;

    // per-thread cp.async coordinates (2 A chunks + 2 B chunks of 16B)
    const int am0 = t >> 3,          akq0 = t & 7;
    const int am1 = (t + 512) >> 3,  akq1 = (t + 512) & 7;
    const int bk0 = t >> 5,          bn40 = t & 31;
    const int bk1 = (t + 512) >> 5,  bn41 = (t + 512) & 31;
    const float* agp0 = A + (size_t)(bm + am0) * K + akq0 * 4;
    const float* agp1 = A + (size_t)(bm + am1) * K + akq1 * 4;
    const float* bgp0 = W + (size_t)bk0 * Nc + bn + bn40 * 4;
    const float* bgp1 = W + (size_t)bk1 * Nc + bn + bn41 * 4;
    const uint32_t as0 = (uint32_t)(am0 * ASTRIDE + akq0 * 4) * 4;
    const uint32_t as1 = (uint32_t)(am1 * ASTRIDE + akq1 * 4) * 4;
    const uint32_t bs0 = (uint32_t)(A_FL + bk0 * BSTRIDE + bn40 * 4) * 4;
    const uint32_t bs1 = (uint32_t)(A_FL + bk1 * BSTRIDE + bn41 * 4) * 4;

    float acc[2][4][4];
    #pragma unroll
    for (int mt = 0; mt < 2; mt++)
        #pragma unroll
        for (int nt = 0; nt < 4; nt++)
            #pragma unroll
            for (int i = 0; i < 4; i++) acc[mt][nt][i] = 0.f;

    // prologue: stages 0..STAGES-2
    #pragma unroll
    for (int c = 0; c < STAGES - 1; c++) {
        uint32_t so = smb + (uint32_t)(c % STAGES) * (STAGE_FL * 4);
        cp16(so + as0, agp0 + c * 32);
        cp16(so + as1, agp1 + c * 32);
        cp16(so + bs0, bgp0 + (size_t)c * 32 * Nc);
        cp16(so + bs1, bgp1 + (size_t)c * 32 * Nc);
        asm volatile("cp.async.commit_group;" ::: "memory");
    }

    for (int c = 0; c < NC; c++) {
        asm volatile("cp.async.wait_group 2;" ::: "memory");
        __syncthreads();

        const int pf = c + STAGES - 1;
        if (pf < NC) {
            uint32_t so = smb + (uint32_t)(pf % STAGES) * (STAGE_FL * 4);
            cp16(so + as0, agp0 + pf * 32);
            cp16(so + as1, agp1 + pf * 32);
            cp16(so + bs0, bgp0 + (size_t)pf * 32 * Nc);
            cp16(so + bs1, bgp1 + (size_t)pf * 32 * Nc);
        }
        asm volatile("cp.async.commit_group;" ::: "memory");

        const float* As = sm + (c % STAGES) * STAGE_FL;
        const float* Bs = As + A_FL;

        #pragma unroll
        for (int ks = 0; ks < 4; ks++) {
            const int krow = ks * 8 + (lane & 3);
            uint32_t af[2][4], bf[4][2];
            #pragma unroll
            for (int mt = 0; mt < 2; mt++) {
                int r = wm * 32 + mt * 16 + (lane >> 2);
                af[mt][0] = __float_as_uint(As[(r    ) * ASTRIDE + krow    ]);
                af[mt][1] = __float_as_uint(As[(r + 8) * ASTRIDE + krow    ]);
                af[mt][2] = __float_as_uint(As[(r    ) * ASTRIDE + krow + 4]);
                af[mt][3] = __float_as_uint(As[(r + 8) * ASTRIDE + krow + 4]);
            }
            #pragma unroll
            for (int nt = 0; nt < 4; nt++) {
                int cn = wn * 32 + nt * 8 + (lane >> 2);
                bf[nt][0] = __float_as_uint(Bs[(krow    ) * BSTRIDE + cn]);
                bf[nt][1] = __float_as_uint(Bs[(krow + 4) * BSTRIDE + cn]);
            }
            #pragma unroll
            for (int mt = 0; mt < 2; mt++)
                #pragma unroll
                for (int nt = 0; nt < 4; nt++)
                    mma_tf32(acc[mt][nt], af[mt], bf[nt]);
        }
    }

    // epilogue
    #pragma unroll
    for (int mt = 0; mt < 2; mt++) {
        #pragma unroll
        for (int half = 0; half < 2; half++) {
            size_t row = (size_t)bm + wm * 32 + mt * 16 + (lane >> 2) + half * 8;
            #pragma unroll
            for (int nt = 0; nt < 4; nt++) {
                int col = bn + wn * 32 + nt * 8 + 2 * (lane & 3);
                float vx = acc[mt][nt][half * 2 + 0];
                float vy = acc[mt][nt][half * 2 + 1];
                if (EPI >= 1) {
                    vx += bias[col];
                    vy += bias[col + 1];
                }
                if (EPI == 1) {
                    const float2 rr = *reinterpret_cast<const float2*>(res + row * Nc + col);
                    vx += rr.x; vy += rr.y;
                }
                if (EPI == 2) {
                    const float kk = 0.70710678118654752f;
                    vx = 0.5f * vx * (1.f + erff(vx * kk));
                    vy = 0.5f * vy * (1.f + erff(vy * kk));
                }
                if (ROUND) { vx = to_tf32(vx); vy = to_tf32(vy); }
                float2 o; o.x = vx; o.y = vy;
                *reinterpret_cast<float2*>(C + row * Nc + col) = o;
            }
        }
    }
}

// ---------------- tensor-core flash attention --------------------------------
// CTA: one (b,h), 64 q-rows; 4 warps x 16 rows. QKV pre-rounded to tf32.
#define AST 68
#define ATT_SMEM ((2 * 64 * AST + 4 * 16 * AST) * 4)

__global__ __launch_bounds__(128) void attn_tc(
    const float* __restrict__ qkv, float* __restrict__ out)
{
    extern __shared__ float smf[];
    float* sK = smf;
    float* sV = smf + 64 * AST;
    const int t = threadIdx.x, lane = t & 31, wid = t >> 5;
    float* sP = smf + 2 * 64 * AST + wid * 16 * AST;

    const int bh = blockIdx.x;
    const int b  = bh / NHEADS;
    const int h  = bh % NHEADS;
    const int q0 = blockIdx.y * 64;

    const int qr = lane >> 2;
    const int qc = lane & 3;
    const int r0 = q0 + wid * 16 + qr;

    // Q fragments (input already tf32; *0.125 is exact)
    uint32_t aq[8][4];
    {
        const float* Q0 = qkv + ((size_t)(b * SEQ + r0)) * (3 * DIMN) + h * HD;
        const float* Q8 = Q0 + 8 * (3 * DIMN);
        #pragma unroll
        for (int kc = 0; kc < 8; kc++) {
            int k_ = kc * 8 + qc;
            aq[kc][0] = __float_as_uint(Q0[k_]     * 0.125f);
            aq[kc][1] = __float_as_uint(Q8[k_]     * 0.125f);
            aq[kc][2] = __float_as_uint(Q0[k_ + 4] * 0.125f);
            aq[kc][3] = __float_as_uint(Q8[k_ + 4] * 0.125f);
        }
    }

    float m0 = -1e30f, m1 = -1e30f, l0 = 0.f, l1 = 0.f;
    float o[8][4];
    #pragma unroll
    for (int nt = 0; nt < 8; nt++)
        #pragma unroll
        for (int i = 0; i < 4; i++) o[nt][i] = 0.f;

    for (int kt = 0; kt < SEQ / 64; kt++) {
        __syncthreads();
        #pragma unroll
        for (int i = 0; i < 8; i++) {
            int idx = t + i * 128;
            int row = idx >> 4, c4 = idx & 15;
            const float* kb = qkv + ((size_t)(b * SEQ + kt * 64 + row)) * (3 * DIMN)
                              + DIMN + h * HD;
            *reinterpret_cast<float4*>(sK + row * AST + c4 * 4) =
                *reinterpret_cast<const float4*>(kb + c4 * 4);
            *reinterpret_cast<float4*>(sV + row * AST + c4 * 4) =
                *reinterpret_cast<const float4*>(kb + DIMN + c4 * 4);
        }
        __syncthreads();

        // S = Q K^T
        float s[8][4];
        #pragma unroll
        for (int nt = 0; nt < 8; nt++)
            #pragma unroll
            for (int i = 0; i < 4; i++) s[nt][i] = 0.f;
        #pragma unroll
        for (int kc = 0; kc < 8; kc++) {
            #pragma unroll
            for (int nt = 0; nt < 8; nt++) {
                uint32_t bk[2];
                const float* kp = sK + (nt * 8 + qr) * AST + kc * 8 + qc;
                bk[0] = __float_as_uint(kp[0]);
                bk[1] = __float_as_uint(kp[4]);
                mma_tf32(s[nt], aq[kc], bk);
            }
        }

        // online softmax
        float mx0 = -1e30f, mx1 = -1e30f;
        #pragma unroll
        for (int nt = 0; nt < 8; nt++) {
            mx0 = fmaxf(mx0, fmaxf(s[nt][0], s[nt][1]));
            mx1 = fmaxf(mx1, fmaxf(s[nt][2], s[nt][3]));
        }
        mx0 = fmaxf(mx0, __shfl_xor_sync(0xFFFFFFFFu, mx0, 1));
        mx0 = fmaxf(mx0, __shfl_xor_sync(0xFFFFFFFFu, mx0, 2));
        mx1 = fmaxf(mx1, __shfl_xor_sync(0xFFFFFFFFu, mx1, 1));
        mx1 = fmaxf(mx1, __shfl_xor_sync(0xFFFFFFFFu, mx1, 2));

        float mn0 = fmaxf(m0, mx0), mn1 = fmaxf(m1, mx1);
        float al0 = __expf(m0 - mn0), al1 = __expf(m1 - mn1);
        m0 = mn0; m1 = mn1;

        float sum0 = 0.f, sum1 = 0.f;
        #pragma unroll
        for (int nt = 0; nt < 8; nt++) {
            s[nt][0] = __expf(s[nt][0] - m0);
            s[nt][1] = __expf(s[nt][1] - m0);
            s[nt][2] = __expf(s[nt][2] - m1);
            s[nt][3] = __expf(s[nt][3] - m1);
            sum0 += s[nt][0] + s[nt][1];
            sum1 += s[nt][2] + s[nt][3];
        }
        sum0 += __shfl_xor_sync(0xFFFFFFFFu, sum0, 1);
        sum0 += __shfl_xor_sync(0xFFFFFFFFu, sum0, 2);
        sum1 += __shfl_xor_sync(0xFFFFFFFFu, sum1, 1);
        sum1 += __shfl_xor_sync(0xFFFFFFFFu, sum1, 2);
        l0 = l0 * al0 + sum0;
        l1 = l1 * al1 + sum1;

        #pragma unroll
        for (int nt = 0; nt < 8; nt++) {
            o[nt][0] *= al0; o[nt][1] *= al0;
            o[nt][2] *= al1; o[nt][3] *= al1;
        }

        // P -> smem (tf32)
        #pragma unroll
        for (int nt = 0; nt < 8; nt++) {
            float2 p01, p23;
            p01.x = to_tf32(s[nt][0]); p01.y = to_tf32(s[nt][1]);
            p23.x = to_tf32(s[nt][2]); p23.y = to_tf32(s[nt][3]);
            *reinterpret_cast<float2*>(sP + qr * AST + nt * 8 + 2 * qc) = p01;
            *reinterpret_cast<float2*>(sP + (qr + 8) * AST + nt * 8 + 2 * qc) = p23;
        }
        __syncwarp();

        // O += P V
        #pragma unroll
        for (int kc = 0; kc < 8; kc++) {
            uint32_t ap[4];
            ap[0] = __float_as_uint(sP[(qr    ) * AST + kc * 8 + qc    ]);
            ap[1] = __float_as_uint(sP[(qr + 8) * AST + kc * 8 + qc    ]);
            ap[2] = __float_as_uint(sP[(qr    ) * AST + kc * 8 + qc + 4]);
            ap[3] = __float_as_uint(sP[(qr + 8) * AST + kc * 8 + qc + 4]);
            #pragma unroll
            for (int nt = 0; nt < 8; nt++) {
                uint32_t bv[2];
                bv[0] = __float_as_uint(sV[(kc * 8 + qc    ) * AST + nt * 8 + qr]);
                bv[1] = __float_as_uint(sV[(kc * 8 + qc + 4) * AST + nt * 8 + qr]);
                mma_tf32(o[nt], ap, bv);
            }
        }
        __syncwarp();
    }

    // normalize + tf32-round + store (feeds proj GEMM A)
    float inv0 = 1.0f / l0, inv1 = 1.0f / l1;
    float* O0 = out + ((size_t)(b * SEQ + r0)) * DIMN + h * HD;
    float* O8 = O0 + 8 * DIMN;
    #pragma unroll
    for (int nt = 0; nt < 8; nt++) {
        int col = nt * 8 + 2 * qc;
        float2 r01, r23;
        r01.x = to_tf32(o[nt][0] * inv0); r01.y = to_tf32(o[nt][1] * inv0);
        r23.x = to_tf32(o[nt][2] * inv1); r23.y = to_tf32(o[nt][3] * inv1);
        *reinterpret_cast<float2*>(O0 + col) = r01;
        *reinterpret_cast<float2*>(O8 + col) = r23;
    }
}

// ---------------- launch ----------------------------------------------------
extern "C" void kernel_launch(void* const* d_in, const int* in_sizes, int n_in,
                              void* d_out, int out_size)
{
    (void)in_sizes; (void)n_in; (void)out_size;
    const float* x      = (const float*)d_in[0];
    const float* w_qkv  = (const float*)d_in[1];
    const float* w_proj = (const float*)d_in[2];
    const float* b_proj = (const float*)d_in[3];
    const float* ln1_g  = (const float*)d_in[4];
    const float* ln1_b  = (const float*)d_in[5];
    const float* w1     = (const float*)d_in[6];
    const float* b1     = (const float*)d_in[7];
    const float* w2     = (const float*)d_in[8];
    const float* b2     = (const float*)d_in[9];
    const float* ln2_g  = (const float*)d_in[10];
    const float* ln2_b  = (const float*)d_in[11];
    float* out = (float*)d_out;

    float *p_h, *p_qkv, *p_o, *p_x1, *p_ffn, *p_wq, *p_wp, *p_w1, *p_w2;
    cudaGetSymbolAddress((void**)&p_h,   g_h);
    cudaGetSymbolAddress((void**)&p_qkv, g_qkv);
    cudaGetSymbolAddress((void**)&p_o,   g_o);
    cudaGetSymbolAddress((void**)&p_x1,  g_x1);
    cudaGetSymbolAddress((void**)&p_ffn, g_ffn);
    cudaGetSymbolAddress((void**)&p_wq,  g_wq);
    cudaGetSymbolAddress((void**)&p_wp,  g_wp);
    cudaGetSymbolAddress((void**)&p_w1,  g_w1c);
    cudaGetSymbolAddress((void**)&p_w2,  g_w2c);

    cudaFuncSetAttribute(gemm_tc<0,1>, cudaFuncAttributeMaxDynamicSharedMemorySize, GEMM_SMEM);
    cudaFuncSetAttribute(gemm_tc<1,0>, cudaFuncAttributeMaxDynamicSharedMemorySize, GEMM_SMEM);
    cudaFuncSetAttribute(gemm_tc<2,1>, cudaFuncAttributeMaxDynamicSharedMemorySize, GEMM_SMEM);
    cudaFuncSetAttribute(attn_tc,      cudaFuncAttributeMaxDynamicSharedMemorySize, ATT_SMEM);

    // 0) one-shot weight tf32 rounding
    cvt_copy<<<(3*DIMN*DIMN)/1024, 256>>>(w_qkv,  p_wq);
    cvt_copy<<<(DIMN*DIMN)/1024,   256>>>(w_proj, p_wp);
    cvt_copy<<<(DIMN*HIDDEN)/1024, 256>>>(w1,     p_w1);
    cvt_copy<<<(DIMN*HIDDEN)/1024, 256>>>(w2,     p_w2);

    // 1) LN1 (tf32 out)
    ln_kernel<<<MROWS, 256>>>(x, ln1_g, ln1_b, p_h);
    // 2) QKV projection (tf32 out -> attention)
    gemm_tc<0,1><<<dim3(3*DIMN/128, MROWS/128), 512, GEMM_SMEM>>>(p_h, p_wq, nullptr, nullptr, p_qkv, DIMN, 3*DIMN);
    // 3) attention (tf32 out -> proj A)
    attn_tc<<<dim3(BB*NHEADS, SEQ/64), 128, ATT_SMEM>>>(p_qkv, p_o);
    // 4) output projection + bias + residual (fp32 out)
    gemm_tc<1,0><<<dim3(DIMN/128, MROWS/128), 512, GEMM_SMEM>>>(p_o, p_wp, b_proj, x, p_x1, DIMN, DIMN);
    // 5) LN2 (tf32 out)
    ln_kernel<<<MROWS, 256>>>(p_x1, ln2_g, ln2_b, p_h);
    // 6) FFN up + GELU (tf32 out)
    gemm_tc<2,1><<<dim3(HIDDEN/128, MROWS/128), 512, GEMM_SMEM>>>(p_h, p_w1, b1, nullptr, p_ffn, DIMN, HIDDEN);
    // 7) FFN down + bias + residual (fp32 out)
    gemm_tc<1,0><<<dim3(DIMN/128, MROWS/128), 512, GEMM_SMEM>>>(p_ffn, p_w2, b2, p_x1, out, HIDDEN, DIMN);
}

// round 6
// speedup vs baseline: 5.7497x; 1.1024x over previous
#include <cuda_runtime.h>
#include <math.h>
#include <stdint.h>

#define DIMN    1024
#define NHEADS  16
#define HD      64
#define HIDDEN  4096
#define BB      4
#define SEQ     2048
#define MROWS   (BB*SEQ)   // 8192

// ---------------- scratch (device globals; no allocation allowed) ----------
__device__ float g_h   [(size_t)MROWS*DIMN];
__device__ float g_qkv [(size_t)MROWS*3*DIMN];
__device__ float g_o   [(size_t)MROWS*DIMN];
__device__ float g_x1  [(size_t)MROWS*DIMN];
__device__ float g_ffn [(size_t)MROWS*HIDDEN];
__device__ float g_wq  [(size_t)DIMN*3*DIMN];
__device__ float g_wp  [(size_t)DIMN*DIMN];
__device__ float g_w1c [(size_t)DIMN*HIDDEN];
__device__ float g_w2c [(size_t)DIMN*HIDDEN];

// ---------------- helpers ----------------------------------------------------
__device__ __forceinline__ float to_tf32(float x) {
    float r;
    asm("cvt.rna.tf32.f32 %0, %1;" : "=f"(r) : "f"(x));
    return r;
}
__device__ __forceinline__ float4 cvt4(float4 v) {
    v.x = to_tf32(v.x); v.y = to_tf32(v.y);
    v.z = to_tf32(v.z); v.w = to_tf32(v.w);
    return v;
}
__device__ __forceinline__ uint32_t smem_u32(const void* p) {
    uint32_t a;
    asm("{ .reg .u64 t; cvta.to.shared.u64 t, %1; cvt.u32.u64 %0, t; }"
        : "=r"(a) : "l"(p));
    return a;
}
__device__ __forceinline__ void cp16(uint32_t s, const float* g) {
    asm volatile("cp.async.cg.shared.global [%0], [%1], 16;" :: "r"(s), "l"(g) : "memory");
}
__device__ __forceinline__ void mma_tf32(float* d, const uint32_t* a, const uint32_t* b) {
    asm volatile(
        "mma.sync.aligned.m16n8k8.row.col.f32.tf32.tf32.f32 "
        "{%0,%1,%2,%3}, {%4,%5,%6,%7}, {%8,%9}, {%0,%1,%2,%3};"
        : "+f"(d[0]), "+f"(d[1]), "+f"(d[2]), "+f"(d[3])
        : "r"(a[0]), "r"(a[1]), "r"(a[2]), "r"(a[3]), "r"(b[0]), "r"(b[1]));
}

// ---------------- tf32 cvt copy (weights, one-shot) --------------------------
__global__ __launch_bounds__(256) void cvt_copy(
    const float* __restrict__ in, float* __restrict__ out)
{
    size_t i = ((size_t)blockIdx.x * 256 + threadIdx.x) * 4;
    *reinterpret_cast<float4*>(out + i) =
        cvt4(*reinterpret_cast<const float4*>(in + i));
}

// ---------------- layernorm (emits tf32-rounded output) ---------------------
__device__ __forceinline__ float block_sum(float v, float* red) {
    __syncthreads();
    #pragma unroll
    for (int o = 16; o; o >>= 1) v += __shfl_down_sync(0xFFFFFFFFu, v, o);
    int w = threadIdx.x >> 5;
    if ((threadIdx.x & 31) == 0) red[w] = v;
    __syncthreads();
    if (threadIdx.x < 32) {
        v = (threadIdx.x < 8) ? red[threadIdx.x] : 0.f;
        #pragma unroll
        for (int o = 4; o; o >>= 1) v += __shfl_down_sync(0xFFFFFFFFu, v, o);
        if (threadIdx.x == 0) red[0] = v;
    }
    __syncthreads();
    return red[0];
}

__global__ __launch_bounds__(256) void ln_kernel(
    const float* __restrict__ in, const float* __restrict__ g,
    const float* __restrict__ b, float* __restrict__ out)
{
    __shared__ float red[32];
    size_t row = blockIdx.x;
    const float4* xr = reinterpret_cast<const float4*>(in + row * DIMN);
    int t = threadIdx.x;
    float4 v = xr[t];

    float s = v.x + v.y + v.z + v.w;
    float mean = block_sum(s, red) * (1.0f / DIMN);

    float dx = v.x - mean, dy = v.y - mean, dz = v.z - mean, dw = v.w - mean;
    float sq = dx*dx + dy*dy + dz*dz + dw*dw;
    float var = block_sum(sq, red) * (1.0f / DIMN);
    float rs = rsqrtf(var + 1e-5f);

    float4 gg = reinterpret_cast<const float4*>(g)[t];
    float4 bb = reinterpret_cast<const float4*>(b)[t];
    float4 o;
    o.x = to_tf32(dx * rs * gg.x + bb.x);
    o.y = to_tf32(dy * rs * gg.y + bb.y);
    o.z = to_tf32(dz * rs * gg.z + bb.z);
    o.w = to_tf32(dw * rs * gg.w + bb.w);
    reinterpret_cast<float4*>(out + row * DIMN)[t] = o;
}

// ---------------- tf32 tensor-core GEMM, cp.async 4-stage --------------------
// 512 thr = 16 warps, CTA tile 256x128, warp tile 64x32 (4 M x 4 N warps).
// K-chunk 32. Inputs A and W pre-rounded to tf32.
// EPI: 0 plain, 1 +bias+residual, 2 +bias+GELU.  ROUND: tf32-round the store.
#define STAGES   4
#define ASTRIDE  36
#define BSTRIDE  136
#define A_FL     (256 * ASTRIDE)            // 9216 floats
#define B_FL     (32 * BSTRIDE)             // 4352 floats
#define STAGE_FL (A_FL + B_FL)              // 13568 floats
#define GEMM_SMEM (STAGES * STAGE_FL * 4)   // 217088 bytes

template<int EPI, int ROUND>
__global__ __launch_bounds__(512, 1) void gemm_tc(
    const float* __restrict__ A, const float* __restrict__ W,
    const float* __restrict__ bias, const float* __restrict__ res,
    float* __restrict__ C, int K, int Nc)
{
    extern __shared__ float sm[];
    const uint32_t smb = smem_u32(sm);

    const int t    = threadIdx.x;
    const int lane = t & 31;
    const int wid  = t >> 5;
    const int wm   = wid & 3;           // warp M tile (64 rows)
    const int wn   = wid >> 2;          // warp N tile (32 cols)
    const int bm   = blockIdx.y * 256;
    const int bn   = blockIdx.x * 128;
    const int NC   = K >> 5;

    // cp.async coords: A = 256 rows x 8 float4 = 2048 -> 4/thread
    //                  B = 32 rows x 32 float4 = 1024 -> 2/thread
    int amr[4], akq[4];
    const float* agp[4];
    uint32_t aso[4];
    #pragma unroll
    for (int i = 0; i < 4; i++) {
        int idx = t + i * 512;
        amr[i] = idx >> 3; akq[i] = idx & 7;
        agp[i] = A + (size_t)(bm + amr[i]) * K + akq[i] * 4;
        aso[i] = (uint32_t)(amr[i] * ASTRIDE + akq[i] * 4) * 4;
    }
    int bkr[2], bn4[2];
    const float* bgp[2];
    uint32_t bso[2];
    #pragma unroll
    for (int i = 0; i < 2; i++) {
        int idx = t + i * 512;
        bkr[i] = idx >> 5; bn4[i] = idx & 31;
        bgp[i] = W + (size_t)bkr[i] * Nc + bn + bn4[i] * 4;
        bso[i] = (uint32_t)(A_FL + bkr[i] * BSTRIDE + bn4[i] * 4) * 4;
    }

    float acc[4][4][4];
    #pragma unroll
    for (int mt = 0; mt < 4; mt++)
        #pragma unroll
        for (int nt = 0; nt < 4; nt++)
            #pragma unroll
            for (int i = 0; i < 4; i++) acc[mt][nt][i] = 0.f;

    // prologue
    #pragma unroll
    for (int c = 0; c < STAGES - 1; c++) {
        uint32_t so = smb + (uint32_t)(c % STAGES) * (STAGE_FL * 4);
        #pragma unroll
        for (int i = 0; i < 4; i++) cp16(so + aso[i], agp[i] + c * 32);
        #pragma unroll
        for (int i = 0; i < 2; i++) cp16(so + bso[i], bgp[i] + (size_t)c * 32 * Nc);
        asm volatile("cp.async.commit_group;" ::: "memory");
    }

    for (int c = 0; c < NC; c++) {
        asm volatile("cp.async.wait_group 2;" ::: "memory");
        __syncthreads();

        const int pf = c + STAGES - 1;
        if (pf < NC) {
            uint32_t so = smb + (uint32_t)(pf % STAGES) * (STAGE_FL * 4);
            #pragma unroll
            for (int i = 0; i < 4; i++) cp16(so + aso[i], agp[i] + pf * 32);
            #pragma unroll
            for (int i = 0; i < 2; i++) cp16(so + bso[i], bgp[i] + (size_t)pf * 32 * Nc);
        }
        asm volatile("cp.async.commit_group;" ::: "memory");

        const float* As = sm + (c % STAGES) * STAGE_FL;
        const float* Bs = As + A_FL;

        #pragma unroll
        for (int ks = 0; ks < 4; ks++) {
            const int krow = ks * 8 + (lane & 3);
            uint32_t af[4][4], bf[4][2];
            #pragma unroll
            for (int mt = 0; mt < 4; mt++) {
                int r = wm * 64 + mt * 16 + (lane >> 2);
                af[mt][0] = __float_as_uint(As[(r    ) * ASTRIDE + krow    ]);
                af[mt][1] = __float_as_uint(As[(r + 8) * ASTRIDE + krow    ]);
                af[mt][2] = __float_as_uint(As[(r    ) * ASTRIDE + krow + 4]);
                af[mt][3] = __float_as_uint(As[(r + 8) * ASTRIDE + krow + 4]);
            }
            #pragma unroll
            for (int nt = 0; nt < 4; nt++) {
                int cn = wn * 32 + nt * 8 + (lane >> 2);
                bf[nt][0] = __float_as_uint(Bs[(krow    ) * BSTRIDE + cn]);
                bf[nt][1] = __float_as_uint(Bs[(krow + 4) * BSTRIDE + cn]);
            }
            #pragma unroll
            for (int mt = 0; mt < 4; mt++)
                #pragma unroll
                for (int nt = 0; nt < 4; nt++)
                    mma_tf32(acc[mt][nt], af[mt], bf[nt]);
        }
    }

    // epilogue
    #pragma unroll
    for (int mt = 0; mt < 4; mt++) {
        #pragma unroll
        for (int half = 0; half < 2; half++) {
            size_t row = (size_t)bm + wm * 64 + mt * 16 + (lane >> 2) + half * 8;
            #pragma unroll
            for (int nt = 0; nt < 4; nt++) {
                int col = bn + wn * 32 + nt * 8 + 2 * (lane & 3);
                float vx = acc[mt][nt][half * 2 + 0];
                float vy = acc[mt][nt][half * 2 + 1];
                if (EPI >= 1) {
                    vx += bias[col];
                    vy += bias[col + 1];
                }
                if (EPI == 1) {
                    const float2 rr = *reinterpret_cast<const float2*>(res + row * Nc + col);
                    vx += rr.x; vy += rr.y;
                }
                if (EPI == 2) {
                    const float kk = 0.70710678118654752f;
                    vx = 0.5f * vx * (1.f + erff(vx * kk));
                    vy = 0.5f * vy * (1.f + erff(vy * kk));
                }
                if (ROUND) { vx = to_tf32(vx); vy = to_tf32(vy); }
                float2 o; o.x = vx; o.y = vy;
                *reinterpret_cast<float2*>(C + row * Nc + col) = o;
            }
        }
    }
}

// ---------------- tensor-core flash attention --------------------------------
#define AST 68
#define ATT_SMEM ((2 * 64 * AST + 4 * 16 * AST) * 4)

__global__ __launch_bounds__(128) void attn_tc(
    const float* __restrict__ qkv, float* __restrict__ out)
{
    extern __shared__ float smf[];
    float* sK = smf;
    float* sV = smf + 64 * AST;
    const int t = threadIdx.x, lane = t & 31, wid = t >> 5;
    float* sP = smf + 2 * 64 * AST + wid * 16 * AST;

    const int bh = blockIdx.x;
    const int b  = bh / NHEADS;
    const int h  = bh % NHEADS;
    const int q0 = blockIdx.y * 64;

    const int qr = lane >> 2;
    const int qc = lane & 3;
    const int r0 = q0 + wid * 16 + qr;

    uint32_t aq[8][4];
    {
        const float* Q0 = qkv + ((size_t)(b * SEQ + r0)) * (3 * DIMN) + h * HD;
        const float* Q8 = Q0 + 8 * (3 * DIMN);
        #pragma unroll
        for (int kc = 0; kc < 8; kc++) {
            int k_ = kc * 8 + qc;
            aq[kc][0] = __float_as_uint(Q0[k_]     * 0.125f);
            aq[kc][1] = __float_as_uint(Q8[k_]     * 0.125f);
            aq[kc][2] = __float_as_uint(Q0[k_ + 4] * 0.125f);
            aq[kc][3] = __float_as_uint(Q8[k_ + 4] * 0.125f);
        }
    }

    float m0 = -1e30f, m1 = -1e30f, l0 = 0.f, l1 = 0.f;
    float o[8][4];
    #pragma unroll
    for (int nt = 0; nt < 8; nt++)
        #pragma unroll
        for (int i = 0; i < 4; i++) o[nt][i] = 0.f;

    for (int kt = 0; kt < SEQ / 64; kt++) {
        __syncthreads();
        #pragma unroll
        for (int i = 0; i < 8; i++) {
            int idx = t + i * 128;
            int row = idx >> 4, c4 = idx & 15;
            const float* kb = qkv + ((size_t)(b * SEQ + kt * 64 + row)) * (3 * DIMN)
                              + DIMN + h * HD;
            *reinterpret_cast<float4*>(sK + row * AST + c4 * 4) =
                *reinterpret_cast<const float4*>(kb + c4 * 4);
            *reinterpret_cast<float4*>(sV + row * AST + c4 * 4) =
                *reinterpret_cast<const float4*>(kb + DIMN + c4 * 4);
        }
        __syncthreads();

        float s[8][4];
        #pragma unroll
        for (int nt = 0; nt < 8; nt++)
            #pragma unroll
            for (int i = 0; i < 4; i++) s[nt][i] = 0.f;
        #pragma unroll
        for (int kc = 0; kc < 8; kc++) {
            #pragma unroll
            for (int nt = 0; nt < 8; nt++) {
                uint32_t bk[2];
                const float* kp = sK + (nt * 8 + qr) * AST + kc * 8 + qc;
                bk[0] = __float_as_uint(kp[0]);
                bk[1] = __float_as_uint(kp[4]);
                mma_tf32(s[nt], aq[kc], bk);
            }
        }

        float mx0 = -1e30f, mx1 = -1e30f;
        #pragma unroll
        for (int nt = 0; nt < 8; nt++) {
            mx0 = fmaxf(mx0, fmaxf(s[nt][0], s[nt][1]));
            mx1 = fmaxf(mx1, fmaxf(s[nt][2], s[nt][3]));
        }
        mx0 = fmaxf(mx0, __shfl_xor_sync(0xFFFFFFFFu, mx0, 1));
        mx0 = fmaxf(mx0, __shfl_xor_sync(0xFFFFFFFFu, mx0, 2));
        mx1 = fmaxf(mx1, __shfl_xor_sync(0xFFFFFFFFu, mx1, 1));
        mx1 = fmaxf(mx1, __shfl_xor_sync(0xFFFFFFFFu, mx1, 2));

        float mn0 = fmaxf(m0, mx0), mn1 = fmaxf(m1, mx1);
        float al0 = __expf(m0 - mn0), al1 = __expf(m1 - mn1);
        m0 = mn0; m1 = mn1;

        float sum0 = 0.f, sum1 = 0.f;
        #pragma unroll
        for (int nt = 0; nt < 8; nt++) {
            s[nt][0] = __expf(s[nt][0] - m0);
            s[nt][1] = __expf(s[nt][1] - m0);
            s[nt][2] = __expf(s[nt][2] - m1);
            s[nt][3] = __expf(s[nt][3] - m1);
            sum0 += s[nt][0] + s[nt][1];
            sum1 += s[nt][2] + s[nt][3];
        }
        sum0 += __shfl_xor_sync(0xFFFFFFFFu, sum0, 1);
        sum0 += __shfl_xor_sync(0xFFFFFFFFu, sum0, 2);
        sum1 += __shfl_xor_sync(0xFFFFFFFFu, sum1, 1);
        sum1 += __shfl_xor_sync(0xFFFFFFFFu, sum1, 2);
        l0 = l0 * al0 + sum0;
        l1 = l1 * al1 + sum1;

        #pragma unroll
        for (int nt = 0; nt < 8; nt++) {
            o[nt][0] *= al0; o[nt][1] *= al0;
            o[nt][2] *= al1; o[nt][3] *= al1;
        }

        #pragma unroll
        for (int nt = 0; nt < 8; nt++) {
            float2 p01, p23;
            p01.x = to_tf32(s[nt][0]); p01.y = to_tf32(s[nt][1]);
            p23.x = to_tf32(s[nt][2]); p23.y = to_tf32(s[nt][3]);
            *reinterpret_cast<float2*>(sP + qr * AST + nt * 8 + 2 * qc) = p01;
            *reinterpret_cast<float2*>(sP + (qr + 8) * AST + nt * 8 + 2 * qc) = p23;
        }
        __syncwarp();

        #pragma unroll
        for (int kc = 0; kc < 8; kc++) {
            uint32_t ap[4];
            ap[0] = __float_as_uint(sP[(qr    ) * AST + kc * 8 + qc    ]);
            ap[1] = __float_as_uint(sP[(qr + 8) * AST + kc * 8 + qc    ]);
            ap[2] = __float_as_uint(sP[(qr    ) * AST + kc * 8 + qc + 4]);
            ap[3] = __float_as_uint(sP[(qr + 8) * AST + kc * 8 + qc + 4]);
            #pragma unroll
            for (int nt = 0; nt < 8; nt++) {
                uint32_t bv[2];
                bv[0] = __float_as_uint(sV[(kc * 8 + qc    ) * AST + nt * 8 + qr]);
                bv[1] = __float_as_uint(sV[(kc * 8 + qc + 4) * AST + nt * 8 + qr]);
                mma_tf32(o[nt], ap, bv);
            }
        }
        __syncwarp();
    }

    float inv0 = 1.0f / l0, inv1 = 1.0f / l1;
    float* O0 = out + ((size_t)(b * SEQ + r0)) * DIMN + h * HD;
    float* O8 = O0 + 8 * DIMN;
    #pragma unroll
    for (int nt = 0; nt < 8; nt++) {
        int col = nt * 8 + 2 * qc;
        float2 r01, r23;
        r01.x = to_tf32(o[nt][0] * inv0); r01.y = to_tf32(o[nt][1] * inv0);
        r23.x = to_tf32(o[nt][2] * inv1); r23.y = to_tf32(o[nt][3] * inv1);
        *reinterpret_cast<float2*>(O0 + col) = r01;
        *reinterpret_cast<float2*>(O8 + col) = r23;
    }
}

// ---------------- launch ----------------------------------------------------
extern "C" void kernel_launch(void* const* d_in, const int* in_sizes, int n_in,
                              void* d_out, int out_size)
{
    (void)in_sizes; (void)n_in; (void)out_size;
    const float* x      = (const float*)d_in[0];
    const float* w_qkv  = (const float*)d_in[1];
    const float* w_proj = (const float*)d_in[2];
    const float* b_proj = (const float*)d_in[3];
    const float* ln1_g  = (const float*)d_in[4];
    const float* ln1_b  = (const float*)d_in[5];
    const float* w1     = (const float*)d_in[6];
    const float* b1     = (const float*)d_in[7];
    const float* w2     = (const float*)d_in[8];
    const float* b2     = (const float*)d_in[9];
    const float* ln2_g  = (const float*)d_in[10];
    const float* ln2_b  = (const float*)d_in[11];
    float* out = (float*)d_out;

    float *p_h, *p_qkv, *p_o, *p_x1, *p_ffn, *p_wq, *p_wp, *p_w1, *p_w2;
    cudaGetSymbolAddress((void**)&p_h,   g_h);
    cudaGetSymbolAddress((void**)&p_qkv, g_qkv);
    cudaGetSymbolAddress((void**)&p_o,   g_o);
    cudaGetSymbolAddress((void**)&p_x1,  g_x1);
    cudaGetSymbolAddress((void**)&p_ffn, g_ffn);
    cudaGetSymbolAddress((void**)&p_wq,  g_wq);
    cudaGetSymbolAddress((void**)&p_wp,  g_wp);
    cudaGetSymbolAddress((void**)&p_w1,  g_w1c);
    cudaGetSymbolAddress((void**)&p_w2,  g_w2c);

    cudaFuncSetAttribute(gemm_tc<0,1>, cudaFuncAttributeMaxDynamicSharedMemorySize, GEMM_SMEM);
    cudaFuncSetAttribute(gemm_tc<1,0>, cudaFuncAttributeMaxDynamicSharedMemorySize, GEMM_SMEM);
    cudaFuncSetAttribute(gemm_tc<2,1>, cudaFuncAttributeMaxDynamicSharedMemorySize, GEMM_SMEM);
    cudaFuncSetAttribute(attn_tc,      cudaFuncAttributeMaxDynamicSharedMemorySize, ATT_SMEM);

    // 0) one-shot weight tf32 rounding
    cvt_copy<<<(3*DIMN*DIMN)/1024, 256>>>(w_qkv,  p_wq);
    cvt_copy<<<(DIMN*DIMN)/1024,   256>>>(w_proj, p_wp);
    cvt_copy<<<(DIMN*HIDDEN)/1024, 256>>>(w1,     p_w1);
    cvt_copy<<<(DIMN*HIDDEN)/1024, 256>>>(w2,     p_w2);

    // 1) LN1 (tf32 out)
    ln_kernel<<<MROWS, 256>>>(x, ln1_g, ln1_b, p_h);
    // 2) QKV projection (tf32 out -> attention)
    gemm_tc<0,1><<<dim3(3*DIMN/128, MROWS/256), 512, GEMM_SMEM>>>(p_h, p_wq, nullptr, nullptr, p_qkv, DIMN, 3*DIMN);
    // 3) attention (tf32 out -> proj A)
    attn_tc<<<dim3(BB*NHEADS, SEQ/64), 128, ATT_SMEM>>>(p_qkv, p_o);
    // 4) output projection + bias + residual (fp32 out)
    gemm_tc<1,0><<<dim3(DIMN/128, MROWS/256), 512, GEMM_SMEM>>>(p_o, p_wp, b_proj, x, p_x1, DIMN, DIMN);
    // 5) LN2 (tf32 out)
    ln_kernel<<<MROWS, 256>>>(p_x1, ln2_g, ln2_b, p_h);
    // 6) FFN up + GELU (tf32 out)
    gemm_tc<2,1><<<dim3(HIDDEN/128, MROWS/256), 512, GEMM_SMEM>>>(p_h, p_w1, b1, nullptr, p_ffn, DIMN, HIDDEN);
    // 7) FFN down + bias + residual (fp32 out)
    gemm_tc<1,0><<<dim3(DIMN/128, MROWS/256), 512, GEMM_SMEM>>>(p_ffn, p_w2, b2, p_x1, out, HIDDEN, DIMN);
}

// round 7
// speedup vs baseline: 9.9652x; 1.7331x over previous
#include <cuda_runtime.h>
#include <cuda_fp16.h>
#include <math.h>
#include <stdint.h>

#define DIMN    1024
#define NHEADS  16
#define HD      64
#define HIDDEN  4096
#define BB      4
#define SEQ     2048
#define MROWS   (BB*SEQ)   // 8192

// ---------------- scratch (device globals; no allocation allowed) ----------
__device__ __half g_h   [(size_t)MROWS*DIMN];
__device__ __half g_qkv [(size_t)MROWS*3*DIMN];
__device__ __half g_o   [(size_t)MROWS*DIMN];
__device__ float  g_x1  [(size_t)MROWS*DIMN];
__device__ __half g_ffn [(size_t)MROWS*HIDDEN];
__device__ __half g_wq  [(size_t)DIMN*3*DIMN];   // [3072][1024] = W_qkv^T
__device__ __half g_wp  [(size_t)DIMN*DIMN];     // [1024][1024]
__device__ __half g_w1t [(size_t)DIMN*HIDDEN];   // [4096][1024]
__device__ __half g_w2t [(size_t)DIMN*HIDDEN];   // [1024][4096]

// ---------------- helpers ----------------------------------------------------
__device__ __forceinline__ uint32_t smem_u32(const void* p) {
    uint32_t a;
    asm("{ .reg .u64 t; cvta.to.shared.u64 t, %1; cvt.u32.u64 %0, t; }"
        : "=r"(a) : "l"(p));
    return a;
}
__device__ __forceinline__ void cp16(uint32_t s, const void* g) {
    asm volatile("cp.async.cg.shared.global [%0], [%1], 16;" :: "r"(s), "l"(g) : "memory");
}
__device__ __forceinline__ void mma_f16(float* d, const uint32_t* a, const uint32_t* b) {
    asm volatile(
        "mma.sync.aligned.m16n8k16.row.col.f32.f16.f16.f32 "
        "{%0,%1,%2,%3}, {%4,%5,%6,%7}, {%8,%9}, {%0,%1,%2,%3};"
        : "+f"(d[0]), "+f"(d[1]), "+f"(d[2]), "+f"(d[3])
        : "r"(a[0]), "r"(a[1]), "r"(a[2]), "r"(a[3]), "r"(b[0]), "r"(b[1]));
}
__device__ __forceinline__ uint32_t ldsm_u32(const __half* p) {
    return *reinterpret_cast<const uint32_t*>(p);
}

// ---------------- weight transpose + fp16 convert (one-shot) -----------------
// in: [K][N] fp32 row-major  ->  out: [N][K] fp16 row-major
__global__ __launch_bounds__(256) void cvt_transpose(
    const float* __restrict__ in, __half* __restrict__ out, int K, int N)
{
    __shared__ float tile[32][33];
    int kx = blockIdx.y * 32, nx = blockIdx.x * 32;
    int tx = threadIdx.x, ty = threadIdx.y;   // (32, 8)
    #pragma unroll
    for (int i = 0; i < 4; i++)
        tile[ty + 8*i][tx] = in[(size_t)(kx + ty + 8*i) * N + nx + tx];
    __syncthreads();
    #pragma unroll
    for (int i = 0; i < 4; i++)
        out[(size_t)(nx + ty + 8*i) * K + kx + tx] = __float2half(tile[tx][ty + 8*i]);
}

// ---------------- layernorm (fp32 in -> fp16 out) ---------------------------
__device__ __forceinline__ float block_sum(float v, float* red) {
    __syncthreads();
    #pragma unroll
    for (int o = 16; o; o >>= 1) v += __shfl_down_sync(0xFFFFFFFFu, v, o);
    int w = threadIdx.x >> 5;
    if ((threadIdx.x & 31) == 0) red[w] = v;
    __syncthreads();
    if (threadIdx.x < 32) {
        v = (threadIdx.x < 8) ? red[threadIdx.x] : 0.f;
        #pragma unroll
        for (int o = 4; o; o >>= 1) v += __shfl_down_sync(0xFFFFFFFFu, v, o);
        if (threadIdx.x == 0) red[0] = v;
    }
    __syncthreads();
    return red[0];
}

__global__ __launch_bounds__(256) void ln_kernel(
    const float* __restrict__ in, const float* __restrict__ g,
    const float* __restrict__ b, __half* __restrict__ out)
{
    __shared__ float red[32];
    size_t row = blockIdx.x;
    const float4* xr = reinterpret_cast<const float4*>(in + row * DIMN);
    int t = threadIdx.x;
    float4 v = xr[t];

    float s = v.x + v.y + v.z + v.w;
    float mean = block_sum(s, red) * (1.0f / DIMN);

    float dx = v.x - mean, dy = v.y - mean, dz = v.z - mean, dw = v.w - mean;
    float sq = dx*dx + dy*dy + dz*dz + dw*dw;
    float var = block_sum(sq, red) * (1.0f / DIMN);
    float rs = rsqrtf(var + 1e-5f);

    float4 gg = reinterpret_cast<const float4*>(g)[t];
    float4 bb = reinterpret_cast<const float4*>(b)[t];
    __half2 h01 = __floats2half2_rn(dx * rs * gg.x + bb.x, dy * rs * gg.y + bb.y);
    __half2 h23 = __floats2half2_rn(dz * rs * gg.z + bb.z, dw * rs * gg.w + bb.w);
    uint2 st;
    st.x = *reinterpret_cast<uint32_t*>(&h01);
    st.y = *reinterpret_cast<uint32_t*>(&h23);
    reinterpret_cast<uint2*>(out + row * DIMN)[t] = st;
}

// ---------------- fp16 tensor-core GEMM (m16n8k16, cp.async 4-stage) ---------
// C[M,Nc] = A[M,K] @ WT[Nc,K]^T. 512 thr = 16 warps, CTA 256x128, warp 64x32.
// K-chunk 64. EPI: 0 plain, 1 +bias+residual, 2 +bias+GELU. OUTH: 1 = fp16 out.
#define STAGES   4
#define TSTRIDE  72                         // halves per smem row (64 + 8 pad)
#define A_HL     (256 * TSTRIDE)            // 18432 halves
#define B_HL     (128 * TSTRIDE)            // 9216 halves
#define STAGE_HL (A_HL + B_HL)              // 27648 halves
#define GEMM_SMEM (STAGES * STAGE_HL * 2)   // 221184 bytes

template<int EPI, int OUTH>
__global__ __launch_bounds__(512, 1) void gemm_f16(
    const __half* __restrict__ A, const __half* __restrict__ WT,
    const float* __restrict__ bias, const float* __restrict__ res,
    void* __restrict__ Cv, int K, int Nc)
{
    extern __shared__ __half smh[];
    const uint32_t smb = smem_u32(smh);

    const int t    = threadIdx.x;
    const int lane = t & 31;
    const int gr   = lane >> 2;         // group row 0..7
    const int qc   = lane & 3;
    const int wid  = t >> 5;
    const int wm   = wid & 3;           // warp M tile (64 rows)
    const int wn   = wid >> 2;          // warp N tile (32 cols)
    const int bm   = blockIdx.y * 256;
    const int bn   = blockIdx.x * 128;
    const int NC   = K >> 6;            // K/64 chunks

    // cp.async coords: A = 256 rows x 8 (16B) = 2048 -> 4/thr; B = 128 x 8 -> 2/thr
    const __half* agp[4]; uint32_t aso[4];
    #pragma unroll
    for (int i = 0; i < 4; i++) {
        int idx = t + i * 512;
        int r = idx >> 3, c8 = idx & 7;
        agp[i] = A + (size_t)(bm + r) * K + c8 * 8;
        aso[i] = (uint32_t)(r * TSTRIDE + c8 * 8) * 2;
    }
    const __half* bgp[2]; uint32_t bso[2];
    #pragma unroll
    for (int i = 0; i < 2; i++) {
        int idx = t + i * 512;
        int n = idx >> 3, c8 = idx & 7;
        bgp[i] = WT + (size_t)(bn + n) * K + c8 * 8;
        bso[i] = (uint32_t)(A_HL + n * TSTRIDE + c8 * 8) * 2;
    }

    float acc[4][4][4];
    #pragma unroll
    for (int mt = 0; mt < 4; mt++)
        #pragma unroll
        for (int nt = 0; nt < 4; nt++)
            #pragma unroll
            for (int i = 0; i < 4; i++) acc[mt][nt][i] = 0.f;

    // prologue
    #pragma unroll
    for (int c = 0; c < STAGES - 1; c++) {
        uint32_t so = smb + (uint32_t)(c % STAGES) * (STAGE_HL * 2);
        #pragma unroll
        for (int i = 0; i < 4; i++) cp16(so + aso[i], agp[i] + c * 64);
        #pragma unroll
        for (int i = 0; i < 2; i++) cp16(so + bso[i], bgp[i] + c * 64);
        asm volatile("cp.async.commit_group;" ::: "memory");
    }

    for (int c = 0; c < NC; c++) {
        asm volatile("cp.async.wait_group 2;" ::: "memory");
        __syncthreads();

        const int pf = c + STAGES - 1;
        if (pf < NC) {
            uint32_t so = smb + (uint32_t)(pf % STAGES) * (STAGE_HL * 2);
            #pragma unroll
            for (int i = 0; i < 4; i++) cp16(so + aso[i], agp[i] + pf * 64);
            #pragma unroll
            for (int i = 0; i < 2; i++) cp16(so + bso[i], bgp[i] + pf * 64);
        }
        asm volatile("cp.async.commit_group;" ::: "memory");

        const __half* As = smh + (c % STAGES) * STAGE_HL;
        const __half* Bs = As + A_HL;

        #pragma unroll
        for (int ks = 0; ks < 4; ks++) {
            const int kb = ks * 16 + 2 * qc;
            uint32_t af[4][4], bf[4][2];
            #pragma unroll
            for (int mt = 0; mt < 4; mt++) {
                int r = wm * 64 + mt * 16 + gr;
                af[mt][0] = ldsm_u32(As + (r    ) * TSTRIDE + kb    );
                af[mt][1] = ldsm_u32(As + (r + 8) * TSTRIDE + kb    );
                af[mt][2] = ldsm_u32(As + (r    ) * TSTRIDE + kb + 8);
                af[mt][3] = ldsm_u32(As + (r + 8) * TSTRIDE + kb + 8);
            }
            #pragma unroll
            for (int nt = 0; nt < 4; nt++) {
                int n = wn * 32 + nt * 8 + gr;
                bf[nt][0] = ldsm_u32(Bs + n * TSTRIDE + kb    );
                bf[nt][1] = ldsm_u32(Bs + n * TSTRIDE + kb + 8);
            }
            #pragma unroll
            for (int mt = 0; mt < 4; mt++)
                #pragma unroll
                for (int nt = 0; nt < 4; nt++)
                    mma_f16(acc[mt][nt], af[mt], bf[nt]);
        }
    }

    // epilogue
    #pragma unroll
    for (int mt = 0; mt < 4; mt++) {
        #pragma unroll
        for (int half_ = 0; half_ < 2; half_++) {
            size_t row = (size_t)bm + wm * 64 + mt * 16 + gr + half_ * 8;
            #pragma unroll
            for (int nt = 0; nt < 4; nt++) {
                int col = bn + wn * 32 + nt * 8 + 2 * qc;
                float vx = acc[mt][nt][half_ * 2 + 0];
                float vy = acc[mt][nt][half_ * 2 + 1];
                if (EPI >= 1) {
                    vx += bias[col];
                    vy += bias[col + 1];
                }
                if (EPI == 1) {
                    const float2 rr = *reinterpret_cast<const float2*>(res + row * Nc + col);
                    vx += rr.x; vy += rr.y;
                }
                if (EPI == 2) {
                    const float kk = 0.70710678118654752f;
                    vx = 0.5f * vx * (1.f + erff(vx * kk));
                    vy = 0.5f * vy * (1.f + erff(vy * kk));
                }
                if (OUTH) {
                    __half2 h = __floats2half2_rn(vx, vy);
                    *reinterpret_cast<__half2*>((__half*)Cv + row * Nc + col) = h;
                } else {
                    float2 o; o.x = vx; o.y = vy;
                    *reinterpret_cast<float2*>((float*)Cv + row * Nc + col) = o;
                }
            }
        }
    }
}

// ---------------- fp16 tensor-core flash attention ---------------------------
// CTA: one (b,h), 64 q-rows; 4 warps x 16 rows. KV tiles of 64.
#define KST 72   // smem stride in halves

__global__ __launch_bounds__(128) void attn_f16(
    const __half* __restrict__ qkv, __half* __restrict__ out)
{
    __shared__ __half sK [64 * KST];   // [kv][hd]
    __shared__ __half sVT[64 * KST];   // [hd][kv]
    __shared__ __half sPa[4][16 * KST];// per-warp P [qrow][kv]

    const int t = threadIdx.x, lane = t & 31, wid = t >> 5;
    const int gr = lane >> 2, qc = lane & 3;
    __half* sP = sPa[wid];

    const int bh = blockIdx.x;
    const int b  = bh / NHEADS;
    const int h  = bh % NHEADS;
    const int q0 = blockIdx.y * 64;
    const int r0 = q0 + wid * 16 + gr;

    // Q fragments (scaled by 0.125, exact in fp16)
    uint32_t aq[4][4];
    {
        const __half* Q0 = qkv + ((size_t)(b * SEQ + r0)) * (3 * DIMN) + h * HD;
        const __half* Q8 = Q0 + 8 * (3 * DIMN);
        const __half2 sc = __half2half2(__float2half(0.125f));
        #pragma unroll
        for (int kc = 0; kc < 4; kc++) {
            int kb = kc * 16 + 2 * qc;
            __half2 v;
            v = __hmul2(*reinterpret_cast<const __half2*>(Q0 + kb),     sc); aq[kc][0] = *reinterpret_cast<uint32_t*>(&v);
            v = __hmul2(*reinterpret_cast<const __half2*>(Q8 + kb),     sc); aq[kc][1] = *reinterpret_cast<uint32_t*>(&v);
            v = __hmul2(*reinterpret_cast<const __half2*>(Q0 + kb + 8), sc); aq[kc][2] = *reinterpret_cast<uint32_t*>(&v);
            v = __hmul2(*reinterpret_cast<const __half2*>(Q8 + kb + 8), sc); aq[kc][3] = *reinterpret_cast<uint32_t*>(&v);
        }
    }

    float m0 = -1e30f, m1 = -1e30f, l0 = 0.f, l1 = 0.f;
    float o[8][4];
    #pragma unroll
    for (int nt = 0; nt < 8; nt++)
        #pragma unroll
        for (int i = 0; i < 4; i++) o[nt][i] = 0.f;

    for (int kt = 0; kt < SEQ / 64; kt++) {
        __syncthreads();
        // K tile: 64 rows x 64 halves (8 x 16B per row) -> 4 uint4 per thread
        #pragma unroll
        for (int i = 0; i < 4; i++) {
            int idx = t + i * 128;
            int row = idx >> 3, c8 = idx & 7;
            const __half* kb = qkv + ((size_t)(b * SEQ + kt * 64 + row)) * (3 * DIMN)
                               + DIMN + h * HD + c8 * 8;
            *reinterpret_cast<uint4*>(sK + row * KST + c8 * 8) =
                *reinterpret_cast<const uint4*>(kb);
        }
        // V tile transposed: thread handles kv pair p = t&31, hd seg = (t>>5)*16
        {
            int p = t & 31, h0 = (t >> 5) * 16;
            const __half* v0 = qkv + ((size_t)(b * SEQ + kt * 64 + 2 * p)) * (3 * DIMN)
                               + 2 * DIMN + h * HD + h0;
            const __half* v1 = v0 + 3 * DIMN;
            uint4 ra0 = *reinterpret_cast<const uint4*>(v0);
            uint4 ra1 = *reinterpret_cast<const uint4*>(v0 + 8);
            uint4 rb0 = *reinterpret_cast<const uint4*>(v1);
            uint4 rb1 = *reinterpret_cast<const uint4*>(v1 + 8);
            const __half* va = reinterpret_cast<const __half*>(&ra0); // 8 halves
            const __half* vb = reinterpret_cast<const __half*>(&rb0);
            const __half* va2 = reinterpret_cast<const __half*>(&ra1);
            const __half* vb2 = reinterpret_cast<const __half*>(&rb1);
            #pragma unroll
            for (int j = 0; j < 8; j++) {
                __half2 hp = __halves2half2(va[j], vb[j]);
                *reinterpret_cast<__half2*>(sVT + (h0 + j) * KST + 2 * p) = hp;
                __half2 hp2 = __halves2half2(va2[j], vb2[j]);
                *reinterpret_cast<__half2*>(sVT + (h0 + 8 + j) * KST + 2 * p) = hp2;
            }
        }
        __syncthreads();

        // S = Q K^T (16 x 64 per warp)
        float s[8][4];
        #pragma unroll
        for (int nt = 0; nt < 8; nt++)
            #pragma unroll
            for (int i = 0; i < 4; i++) s[nt][i] = 0.f;
        #pragma unroll
        for (int kc = 0; kc < 4; kc++) {
            int kb = kc * 16 + 2 * qc;
            #pragma unroll
            for (int nt = 0; nt < 8; nt++) {
                uint32_t bk[2];
                const __half* kp = sK + (nt * 8 + gr) * KST + kb;
                bk[0] = ldsm_u32(kp);
                bk[1] = ldsm_u32(kp + 8);
                mma_f16(s[nt], aq[kc], bk);
            }
        }

        // online softmax (rows r0 -> c0/c1, r0+8 -> c2/c3)
        float mx0 = -1e30f, mx1 = -1e30f;
        #pragma unroll
        for (int nt = 0; nt < 8; nt++) {
            mx0 = fmaxf(mx0, fmaxf(s[nt][0], s[nt][1]));
            mx1 = fmaxf(mx1, fmaxf(s[nt][2], s[nt][3]));
        }
        mx0 = fmaxf(mx0, __shfl_xor_sync(0xFFFFFFFFu, mx0, 1));
        mx0 = fmaxf(mx0, __shfl_xor_sync(0xFFFFFFFFu, mx0, 2));
        mx1 = fmaxf(mx1, __shfl_xor_sync(0xFFFFFFFFu, mx1, 1));
        mx1 = fmaxf(mx1, __shfl_xor_sync(0xFFFFFFFFu, mx1, 2));

        float mn0 = fmaxf(m0, mx0), mn1 = fmaxf(m1, mx1);
        float al0 = __expf(m0 - mn0), al1 = __expf(m1 - mn1);
        m0 = mn0; m1 = mn1;

        float sum0 = 0.f, sum1 = 0.f;
        #pragma unroll
        for (int nt = 0; nt < 8; nt++) {
            s[nt][0] = __expf(s[nt][0] - m0);
            s[nt][1] = __expf(s[nt][1] - m0);
            s[nt][2] = __expf(s[nt][2] - m1);
            s[nt][3] = __expf(s[nt][3] - m1);
            sum0 += s[nt][0] + s[nt][1];
            sum1 += s[nt][2] + s[nt][3];
        }
        sum0 += __shfl_xor_sync(0xFFFFFFFFu, sum0, 1);
        sum0 += __shfl_xor_sync(0xFFFFFFFFu, sum0, 2);
        sum1 += __shfl_xor_sync(0xFFFFFFFFu, sum1, 1);
        sum1 += __shfl_xor_sync(0xFFFFFFFFu, sum1, 2);
        l0 = l0 * al0 + sum0;
        l1 = l1 * al1 + sum1;

        #pragma unroll
        for (int nt = 0; nt < 8; nt++) {
            o[nt][0] *= al0; o[nt][1] *= al0;
            o[nt][2] *= al1; o[nt][3] *= al1;
        }

        // P -> per-warp smem as fp16
        #pragma unroll
        for (int nt = 0; nt < 8; nt++) {
            int col = nt * 8 + 2 * qc;
            *reinterpret_cast<__half2*>(sP + gr * KST + col) =
                __floats2half2_rn(s[nt][0], s[nt][1]);
            *reinterpret_cast<__half2*>(sP + (gr + 8) * KST + col) =
                __floats2half2_rn(s[nt][2], s[nt][3]);
        }
        __syncwarp();

        // O += P V  (k = kv, 4 chunks of 16)
        #pragma unroll
        for (int kc = 0; kc < 4; kc++) {
            int kb = kc * 16 + 2 * qc;
            uint32_t ap[4];
            ap[0] = ldsm_u32(sP + (gr    ) * KST + kb    );
            ap[1] = ldsm_u32(sP + (gr + 8) * KST + kb    );
            ap[2] = ldsm_u32(sP + (gr    ) * KST + kb + 8);
            ap[3] = ldsm_u32(sP + (gr + 8) * KST + kb + 8);
            #pragma unroll
            for (int nt = 0; nt < 8; nt++) {
                uint32_t bv[2];
                const __half* vp = sVT + (nt * 8 + gr) * KST + kb;
                bv[0] = ldsm_u32(vp);
                bv[1] = ldsm_u32(vp + 8);
                mma_f16(o[nt], ap, bv);
            }
        }
        __syncwarp();
    }

    // normalize + fp16 store (feeds proj GEMM A)
    float inv0 = 1.0f / l0, inv1 = 1.0f / l1;
    __half* O0 = out + ((size_t)(b * SEQ + r0)) * DIMN + h * HD;
    __half* O8 = O0 + 8 * DIMN;
    #pragma unroll
    for (int nt = 0; nt < 8; nt++) {
        int col = nt * 8 + 2 * qc;
        *reinterpret_cast<__half2*>(O0 + col) =
            __floats2half2_rn(o[nt][0] * inv0, o[nt][1] * inv0);
        *reinterpret_cast<__half2*>(O8 + col) =
            __floats2half2_rn(o[nt][2] * inv1, o[nt][3] * inv1);
    }
}

// ---------------- launch ----------------------------------------------------
extern "C" void kernel_launch(void* const* d_in, const int* in_sizes, int n_in,
                              void* d_out, int out_size)
{
    (void)in_sizes; (void)n_in; (void)out_size;
    const float* x      = (const float*)d_in[0];
    const float* w_qkv  = (const float*)d_in[1];
    const float* w_proj = (const float*)d_in[2];
    const float* b_proj = (const float*)d_in[3];
    const float* ln1_g  = (const float*)d_in[4];
    const float* ln1_b  = (const float*)d_in[5];
    const float* w1     = (const float*)d_in[6];
    const float* b1     = (const float*)d_in[7];
    const float* w2     = (const float*)d_in[8];
    const float* b2     = (const float*)d_in[9];
    const float* ln2_g  = (const float*)d_in[10];
    const float* ln2_b  = (const float*)d_in[11];
    float* out = (float*)d_out;

    __half *p_h, *p_qkv, *p_o, *p_ffn, *p_wq, *p_wp, *p_w1, *p_w2;
    float *p_x1;
    cudaGetSymbolAddress((void**)&p_h,   g_h);
    cudaGetSymbolAddress((void**)&p_qkv, g_qkv);
    cudaGetSymbolAddress((void**)&p_o,   g_o);
    cudaGetSymbolAddress((void**)&p_x1,  g_x1);
    cudaGetSymbolAddress((void**)&p_ffn, g_ffn);
    cudaGetSymbolAddress((void**)&p_wq,  g_wq);
    cudaGetSymbolAddress((void**)&p_wp,  g_wp);
    cudaGetSymbolAddress((void**)&p_w1,  g_w1t);
    cudaGetSymbolAddress((void**)&p_w2,  g_w2t);

    cudaFuncSetAttribute(gemm_f16<0,1>, cudaFuncAttributeMaxDynamicSharedMemorySize, GEMM_SMEM);
    cudaFuncSetAttribute(gemm_f16<1,0>, cudaFuncAttributeMaxDynamicSharedMemorySize, GEMM_SMEM);
    cudaFuncSetAttribute(gemm_f16<2,1>, cudaFuncAttributeMaxDynamicSharedMemorySize, GEMM_SMEM);

    // 0) one-shot weight transpose + fp16 convert
    cvt_transpose<<<dim3(3*DIMN/32, DIMN/32),   dim3(32,8)>>>(w_qkv,  p_wq, DIMN,   3*DIMN);
    cvt_transpose<<<dim3(DIMN/32,   DIMN/32),   dim3(32,8)>>>(w_proj, p_wp, DIMN,   DIMN);
    cvt_transpose<<<dim3(HIDDEN/32, DIMN/32),   dim3(32,8)>>>(w1,     p_w1, DIMN,   HIDDEN);
    cvt_transpose<<<dim3(DIMN/32,   HIDDEN/32), dim3(32,8)>>>(w2,     p_w2, HIDDEN, DIMN);

    // 1) LN1 (fp16 out)
    ln_kernel<<<MROWS, 256>>>(x, ln1_g, ln1_b, p_h);
    // 2) QKV projection (fp16 out)
    gemm_f16<0,1><<<dim3(3*DIMN/128, MROWS/256), 512, GEMM_SMEM>>>(p_h, p_wq, nullptr, nullptr, p_qkv, DIMN, 3*DIMN);
    // 3) attention (fp16 out)
    attn_f16<<<dim3(BB*NHEADS, SEQ/64), 128>>>(p_qkv, p_o);
    // 4) output projection + bias + residual (fp32 out)
    gemm_f16<1,0><<<dim3(DIMN/128, MROWS/256), 512, GEMM_SMEM>>>(p_o, p_wp, b_proj, x, p_x1, DIMN, DIMN);
    // 5) LN2 (fp16 out)
    ln_kernel<<<MROWS, 256>>>(p_x1, ln2_g, ln2_b, p_h);
    // 6) FFN up + GELU (fp16 out)
    gemm_f16<2,1><<<dim3(HIDDEN/128, MROWS/256), 512, GEMM_SMEM>>>(p_h, p_w1, b1, nullptr, p_ffn, DIMN, HIDDEN);
    // 7) FFN down + bias + residual (fp32 out)
    gemm_f16<1,0><<<dim3(DIMN/128, MROWS/256), 512, GEMM_SMEM>>>(p_ffn, p_w2, b2, p_x1, out, HIDDEN, DIMN);
}

// round 8
// speedup vs baseline: 11.5667x; 1.1607x over previous
#include <cuda_runtime.h>
#include <cuda_fp16.h>
#include <math.h>
#include <stdint.h>

#define DIMN    1024
#define NHEADS  16
#define HD      64
#define HIDDEN  4096
#define BB      4
#define SEQ     2048
#define MROWS   (BB*SEQ)   // 8192

// ---------------- scratch (device globals; no allocation allowed) ----------
__device__ __half g_h   [(size_t)MROWS*DIMN];
__device__ __half g_qkv [(size_t)MROWS*3*DIMN];
__device__ __half g_o   [(size_t)MROWS*DIMN];
__device__ float  g_x1  [(size_t)MROWS*DIMN];
__device__ __half g_ffn [(size_t)MROWS*HIDDEN];
__device__ __half g_wq  [(size_t)DIMN*3*DIMN];   // W_qkv^T  [3072][1024]
__device__ __half g_wp  [(size_t)DIMN*DIMN];     // W_proj^T [1024][1024]
__device__ __half g_w1t [(size_t)DIMN*HIDDEN];   // W1^T     [4096][1024]
__device__ __half g_w2t [(size_t)DIMN*HIDDEN];   // W2^T     [1024][4096]

// ---------------- helpers ----------------------------------------------------
__device__ __forceinline__ uint32_t smem_u32(const void* p) {
    uint32_t a;
    asm("{ .reg .u64 t; cvta.to.shared.u64 t, %1; cvt.u32.u64 %0, t; }"
        : "=r"(a) : "l"(p));
    return a;
}
__device__ __forceinline__ void cp16(uint32_t s, const void* g) {
    asm volatile("cp.async.cg.shared.global [%0], [%1], 16;" :: "r"(s), "l"(g) : "memory");
}
__device__ __forceinline__ void mma_f16(float* d, const uint32_t* a, const uint32_t* b) {
    asm volatile(
        "mma.sync.aligned.m16n8k16.row.col.f32.f16.f16.f32 "
        "{%0,%1,%2,%3}, {%4,%5,%6,%7}, {%8,%9}, {%0,%1,%2,%3};"
        : "+f"(d[0]), "+f"(d[1]), "+f"(d[2]), "+f"(d[3])
        : "r"(a[0]), "r"(a[1]), "r"(a[2]), "r"(a[3]), "r"(b[0]), "r"(b[1]));
}
__device__ __forceinline__ void ldsm_x4(uint32_t* r, uint32_t addr) {
    asm volatile("ldmatrix.sync.aligned.m8n8.x4.shared.b16 {%0,%1,%2,%3}, [%4];"
        : "=r"(r[0]), "=r"(r[1]), "=r"(r[2]), "=r"(r[3]) : "r"(addr));
}

// ---------------- weight transpose + fp16 convert (one-shot) -----------------
__global__ __launch_bounds__(256) void cvt_transpose(
    const float* __restrict__ in, __half* __restrict__ out, int K, int N)
{
    __shared__ float tile[32][33];
    int kx = blockIdx.y * 32, nx = blockIdx.x * 32;
    int tx = threadIdx.x, ty = threadIdx.y;   // (32, 8)
    #pragma unroll
    for (int i = 0; i < 4; i++)
        tile[ty + 8*i][tx] = in[(size_t)(kx + ty + 8*i) * N + nx + tx];
    __syncthreads();
    #pragma unroll
    for (int i = 0; i < 4; i++)
        out[(size_t)(nx + ty + 8*i) * K + kx + tx] = __float2half(tile[tx][ty + 8*i]);
}

// ---------------- layernorm (fp32 in -> fp16 out) ---------------------------
__device__ __forceinline__ float block_sum(float v, float* red) {
    __syncthreads();
    #pragma unroll
    for (int o = 16; o; o >>= 1) v += __shfl_down_sync(0xFFFFFFFFu, v, o);
    int w = threadIdx.x >> 5;
    if ((threadIdx.x & 31) == 0) red[w] = v;
    __syncthreads();
    if (threadIdx.x < 32) {
        v = (threadIdx.x < 8) ? red[threadIdx.x] : 0.f;
        #pragma unroll
        for (int o = 4; o; o >>= 1) v += __shfl_down_sync(0xFFFFFFFFu, v, o);
        if (threadIdx.x == 0) red[0] = v;
    }
    __syncthreads();
    return red[0];
}

__global__ __launch_bounds__(256) void ln_kernel(
    const float* __restrict__ in, const float* __restrict__ g,
    const float* __restrict__ b, __half* __restrict__ out)
{
    __shared__ float red[32];
    size_t row = blockIdx.x;
    const float4* xr = reinterpret_cast<const float4*>(in + row * DIMN);
    int t = threadIdx.x;
    float4 v = xr[t];

    float s = v.x + v.y + v.z + v.w;
    float mean = block_sum(s, red) * (1.0f / DIMN);

    float dx = v.x - mean, dy = v.y - mean, dz = v.z - mean, dw = v.w - mean;
    float sq = dx*dx + dy*dy + dz*dz + dw*dw;
    float var = block_sum(sq, red) * (1.0f / DIMN);
    float rs = rsqrtf(var + 1e-5f);

    float4 gg = reinterpret_cast<const float4*>(g)[t];
    float4 bb = reinterpret_cast<const float4*>(b)[t];
    __half2 h01 = __floats2half2_rn(dx * rs * gg.x + bb.x, dy * rs * gg.y + bb.y);
    __half2 h23 = __floats2half2_rn(dz * rs * gg.z + bb.z, dw * rs * gg.w + bb.w);
    uint2 st;
    st.x = *reinterpret_cast<uint32_t*>(&h01);
    st.y = *reinterpret_cast<uint32_t*>(&h23);
    reinterpret_cast<uint2*>(out + row * DIMN)[t] = st;
}

// ---------------- fp16 tensor-core GEMM (ldmatrix + cp.async 4-stage) --------
// C[M,Nc] = A[M,K] @ WT[Nc,K]^T. 512 thr = 16 warps, CTA 256x128, warp 64x32.
#define STAGES   4
#define TSTRIDE  72                         // halves per smem row (144 B)
#define A_HL     (256 * TSTRIDE)
#define B_HL     (128 * TSTRIDE)
#define STAGE_HL (A_HL + B_HL)
#define GEMM_SMEM (STAGES * STAGE_HL * 2)   // 221184 bytes

template<int EPI, int OUTH>
__global__ __launch_bounds__(512, 1) void gemm_f16(
    const __half* __restrict__ A, const __half* __restrict__ WT,
    const float* __restrict__ bias, const float* __restrict__ res,
    void* __restrict__ Cv, int K, int Nc)
{
    extern __shared__ __half smh[];
    const uint32_t smb = smem_u32(smh);

    const int t    = threadIdx.x;
    const int lane = t & 31;
    const int gr   = lane >> 2;
    const int qc   = lane & 3;
    const int wid  = t >> 5;
    const int wm   = wid & 3;
    const int wn   = wid >> 2;
    const int bm   = blockIdx.y * 256;
    const int bn   = blockIdx.x * 128;
    const int NC   = K >> 6;

    // ldmatrix lane offsets (bytes)
    const uint32_t a_lo = (uint32_t)((lane & 15) * TSTRIDE + (lane >> 4) * 8) * 2;
    const uint32_t b_lo = (uint32_t)(((lane & 7) + (lane >> 4) * 8) * TSTRIDE
                                     + ((lane >> 3) & 1) * 8) * 2;

    // cp.async coords
    const __half* agp[4]; uint32_t aso[4];
    #pragma unroll
    for (int i = 0; i < 4; i++) {
        int idx = t + i * 512;
        int r = idx >> 3, c8 = idx & 7;
        agp[i] = A + (size_t)(bm + r) * K + c8 * 8;
        aso[i] = (uint32_t)(r * TSTRIDE + c8 * 8) * 2;
    }
    const __half* bgp[2]; uint32_t bso[2];
    #pragma unroll
    for (int i = 0; i < 2; i++) {
        int idx = t + i * 512;
        int n = idx >> 3, c8 = idx & 7;
        bgp[i] = WT + (size_t)(bn + n) * K + c8 * 8;
        bso[i] = (uint32_t)(A_HL + n * TSTRIDE + c8 * 8) * 2;
    }

    float acc[4][4][4];
    #pragma unroll
    for (int mt = 0; mt < 4; mt++)
        #pragma unroll
        for (int nt = 0; nt < 4; nt++)
            #pragma unroll
            for (int i = 0; i < 4; i++) acc[mt][nt][i] = 0.f;

    #pragma unroll
    for (int c = 0; c < STAGES - 1; c++) {
        uint32_t so = smb + (uint32_t)(c % STAGES) * (STAGE_HL * 2);
        #pragma unroll
        for (int i = 0; i < 4; i++) cp16(so + aso[i], agp[i] + c * 64);
        #pragma unroll
        for (int i = 0; i < 2; i++) cp16(so + bso[i], bgp[i] + c * 64);
        asm volatile("cp.async.commit_group;" ::: "memory");
    }

    for (int c = 0; c < NC; c++) {
        asm volatile("cp.async.wait_group 2;" ::: "memory");
        __syncthreads();

        const int pf = c + STAGES - 1;
        if (pf < NC) {
            uint32_t so = smb + (uint32_t)(pf % STAGES) * (STAGE_HL * 2);
            #pragma unroll
            for (int i = 0; i < 4; i++) cp16(so + aso[i], agp[i] + pf * 64);
            #pragma unroll
            for (int i = 0; i < 2; i++) cp16(so + bso[i], bgp[i] + pf * 64);
        }
        asm volatile("cp.async.commit_group;" ::: "memory");

        const uint32_t asb = smb + (uint32_t)(c % STAGES) * (STAGE_HL * 2);
        const uint32_t bsb = asb + A_HL * 2;

        #pragma unroll
        for (int ks = 0; ks < 4; ks++) {
            uint32_t af[4][4], bq[2][4];
            #pragma unroll
            for (int mt = 0; mt < 4; mt++)
                ldsm_x4(af[mt], asb + a_lo +
                        (uint32_t)(((wm * 64 + mt * 16) * TSTRIDE + ks * 16) * 2));
            #pragma unroll
            for (int i = 0; i < 2; i++)
                ldsm_x4(bq[i], bsb + b_lo +
                        (uint32_t)(((wn * 32 + i * 16) * TSTRIDE + ks * 16) * 2));
            #pragma unroll
            for (int mt = 0; mt < 4; mt++)
                #pragma unroll
                for (int nt = 0; nt < 4; nt++)
                    mma_f16(acc[mt][nt], af[mt], &bq[nt >> 1][(nt & 1) * 2]);
        }
    }

    // epilogue
    #pragma unroll
    for (int mt = 0; mt < 4; mt++) {
        #pragma unroll
        for (int half_ = 0; half_ < 2; half_++) {
            size_t row = (size_t)bm + wm * 64 + mt * 16 + gr + half_ * 8;
            #pragma unroll
            for (int nt = 0; nt < 4; nt++) {
                int col = bn + wn * 32 + nt * 8 + 2 * qc;
                float vx = acc[mt][nt][half_ * 2 + 0];
                float vy = acc[mt][nt][half_ * 2 + 1];
                if (EPI >= 1) {
                    vx += bias[col];
                    vy += bias[col + 1];
                }
                if (EPI == 1) {
                    const float2 rr = *reinterpret_cast<const float2*>(res + row * Nc + col);
                    vx += rr.x; vy += rr.y;
                }
                if (EPI == 2) {
                    const float kk = 0.70710678118654752f;
                    vx = 0.5f * vx * (1.f + erff(vx * kk));
                    vy = 0.5f * vy * (1.f + erff(vy * kk));
                }
                if (OUTH) {
                    __half2 h = __floats2half2_rn(vx, vy);
                    *reinterpret_cast<__half2*>((__half*)Cv + row * Nc + col) = h;
                } else {
                    float2 o; o.x = vx; o.y = vy;
                    *reinterpret_cast<float2*>((float*)Cv + row * Nc + col) = o;
                }
            }
        }
    }
}

// ---------------- fp16 flash attention (8 warps, 128 q-rows/CTA) -------------
#define KST 72

__global__ __launch_bounds__(256) void attn_f16(
    const __half* __restrict__ qkv, __half* __restrict__ out)
{
    __shared__ __half sK [64 * KST];
    __shared__ __half sVT[64 * KST];
    __shared__ __half sPa[8][16 * KST];

    const int t = threadIdx.x, lane = t & 31, wid = t >> 5;
    const int gr = lane >> 2, qc = lane & 3;
    __half* sP = sPa[wid];

    const uint32_t sKb  = smem_u32(sK);
    const uint32_t sVTb = smem_u32(sVT);
    const uint32_t sPb  = smem_u32(sP);
    const uint32_t a_lo = (uint32_t)((lane & 15) * KST + (lane >> 4) * 8) * 2;
    const uint32_t b_lo = (uint32_t)(((lane & 7) + (lane >> 4) * 8) * KST
                                     + ((lane >> 3) & 1) * 8) * 2;

    const int bh = blockIdx.x;
    const int b  = bh / NHEADS;
    const int h  = bh % NHEADS;
    const int q0 = blockIdx.y * 128;
    const int r0 = q0 + wid * 16 + gr;

    // Q fragments (scaled by 0.125, exact in fp16)
    uint32_t aq[4][4];
    {
        const __half* Q0 = qkv + ((size_t)(b * SEQ + r0)) * (3 * DIMN) + h * HD;
        const __half* Q8 = Q0 + 8 * (3 * DIMN);
        const __half2 sc = __half2half2(__float2half(0.125f));
        #pragma unroll
        for (int kc = 0; kc < 4; kc++) {
            int kb = kc * 16 + 2 * qc;
            __half2 v;
            v = __hmul2(*reinterpret_cast<const __half2*>(Q0 + kb),     sc); aq[kc][0] = *reinterpret_cast<uint32_t*>(&v);
            v = __hmul2(*reinterpret_cast<const __half2*>(Q8 + kb),     sc); aq[kc][1] = *reinterpret_cast<uint32_t*>(&v);
            v = __hmul2(*reinterpret_cast<const __half2*>(Q0 + kb + 8), sc); aq[kc][2] = *reinterpret_cast<uint32_t*>(&v);
            v = __hmul2(*reinterpret_cast<const __half2*>(Q8 + kb + 8), sc); aq[kc][3] = *reinterpret_cast<uint32_t*>(&v);
        }
    }

    float m0 = -1e30f, m1 = -1e30f, l0 = 0.f, l1 = 0.f;
    float o[8][4];
    #pragma unroll
    for (int nt = 0; nt < 8; nt++)
        #pragma unroll
        for (int i = 0; i < 4; i++) o[nt][i] = 0.f;

    for (int kt = 0; kt < SEQ / 64; kt++) {
        __syncthreads();
        // K tile: 64 rows x 8 (16B) = 512 chunks -> 2/thread
        #pragma unroll
        for (int i = 0; i < 2; i++) {
            int idx = t + i * 256;
            int row = idx >> 3, c8 = idx & 7;
            const __half* kb = qkv + ((size_t)(b * SEQ + kt * 64 + row)) * (3 * DIMN)
                               + DIMN + h * HD + c8 * 8;
            *reinterpret_cast<uint4*>(sK + row * KST + c8 * 8) =
                *reinterpret_cast<const uint4*>(kb);
        }
        // V tile transposed: p = t&31 -> kv rows 2p,2p+1; seg = t>>5 -> hd seg*8
        {
            int p = t & 31, h0 = (t >> 5) * 8;
            const __half* v0 = qkv + ((size_t)(b * SEQ + kt * 64 + 2 * p)) * (3 * DIMN)
                               + 2 * DIMN + h * HD + h0;
            const __half* v1 = v0 + 3 * DIMN;
            uint4 ra = *reinterpret_cast<const uint4*>(v0);
            uint4 rb = *reinterpret_cast<const uint4*>(v1);
            const __half* va = reinterpret_cast<const __half*>(&ra);
            const __half* vb = reinterpret_cast<const __half*>(&rb);
            #pragma unroll
            for (int j = 0; j < 8; j++)
                *reinterpret_cast<__half2*>(sVT + (h0 + j) * KST + 2 * p) =
                    __halves2half2(va[j], vb[j]);
        }
        __syncthreads();

        // S = Q K^T (16 x 64 per warp), K via ldmatrix
        float s[8][4];
        #pragma unroll
        for (int nt = 0; nt < 8; nt++)
            #pragma unroll
            for (int i = 0; i < 4; i++) s[nt][i] = 0.f;
        #pragma unroll
        for (int kc = 0; kc < 4; kc++) {
            #pragma unroll
            for (int i = 0; i < 4; i++) {
                uint32_t bq[4];
                ldsm_x4(bq, sKb + b_lo + (uint32_t)(((i * 16) * KST + kc * 16) * 2));
                mma_f16(s[2*i],   aq[kc], bq);
                mma_f16(s[2*i+1], aq[kc], bq + 2);
            }
        }

        // online softmax
        float mx0 = -1e30f, mx1 = -1e30f;
        #pragma unroll
        for (int nt = 0; nt < 8; nt++) {
            mx0 = fmaxf(mx0, fmaxf(s[nt][0], s[nt][1]));
            mx1 = fmaxf(mx1, fmaxf(s[nt][2], s[nt][3]));
        }
        mx0 = fmaxf(mx0, __shfl_xor_sync(0xFFFFFFFFu, mx0, 1));
        mx0 = fmaxf(mx0, __shfl_xor_sync(0xFFFFFFFFu, mx0, 2));
        mx1 = fmaxf(mx1, __shfl_xor_sync(0xFFFFFFFFu, mx1, 1));
        mx1 = fmaxf(mx1, __shfl_xor_sync(0xFFFFFFFFu, mx1, 2));

        float mn0 = fmaxf(m0, mx0), mn1 = fmaxf(m1, mx1);
        float al0 = __expf(m0 - mn0), al1 = __expf(m1 - mn1);
        m0 = mn0; m1 = mn1;

        float sum0 = 0.f, sum1 = 0.f;
        #pragma unroll
        for (int nt = 0; nt < 8; nt++) {
            s[nt][0] = __expf(s[nt][0] - m0);
            s[nt][1] = __expf(s[nt][1] - m0);
            s[nt][2] = __expf(s[nt][2] - m1);
            s[nt][3] = __expf(s[nt][3] - m1);
            sum0 += s[nt][0] + s[nt][1];
            sum1 += s[nt][2] + s[nt][3];
        }
        sum0 += __shfl_xor_sync(0xFFFFFFFFu, sum0, 1);
        sum0 += __shfl_xor_sync(0xFFFFFFFFu, sum0, 2);
        sum1 += __shfl_xor_sync(0xFFFFFFFFu, sum1, 1);
        sum1 += __shfl_xor_sync(0xFFFFFFFFu, sum1, 2);
        l0 = l0 * al0 + sum0;
        l1 = l1 * al1 + sum1;

        #pragma unroll
        for (int nt = 0; nt < 8; nt++) {
            o[nt][0] *= al0; o[nt][1] *= al0;
            o[nt][2] *= al1; o[nt][3] *= al1;
        }

        // P -> per-warp smem as fp16
        #pragma unroll
        for (int nt = 0; nt < 8; nt++) {
            int col = nt * 8 + 2 * qc;
            *reinterpret_cast<__half2*>(sP + gr * KST + col) =
                __floats2half2_rn(s[nt][0], s[nt][1]);
            *reinterpret_cast<__half2*>(sP + (gr + 8) * KST + col) =
                __floats2half2_rn(s[nt][2], s[nt][3]);
        }
        __syncwarp();

        // O += P V: P via ldmatrix (A), VT via ldmatrix (B)
        #pragma unroll
        for (int kc = 0; kc < 4; kc++) {
            uint32_t ap[4];
            ldsm_x4(ap, sPb + a_lo + (uint32_t)((kc * 16) * 2));
            #pragma unroll
            for (int i = 0; i < 4; i++) {
                uint32_t bq[4];
                ldsm_x4(bq, sVTb + b_lo + (uint32_t)(((i * 16) * KST + kc * 16) * 2));
                mma_f16(o[2*i],   ap, bq);
                mma_f16(o[2*i+1], ap, bq + 2);
            }
        }
        __syncwarp();
    }

    // normalize + fp16 store
    float inv0 = 1.0f / l0, inv1 = 1.0f / l1;
    __half* O0 = out + ((size_t)(b * SEQ + r0)) * DIMN + h * HD;
    __half* O8 = O0 + 8 * DIMN;
    #pragma unroll
    for (int nt = 0; nt < 8; nt++) {
        int col = nt * 8 + 2 * qc;
        *reinterpret_cast<__half2*>(O0 + col) =
            __floats2half2_rn(o[nt][0] * inv0, o[nt][1] * inv0);
        *reinterpret_cast<__half2*>(O8 + col) =
            __floats2half2_rn(o[nt][2] * inv1, o[nt][3] * inv1);
    }
}

// ---------------- launch ----------------------------------------------------
extern "C" void kernel_launch(void* const* d_in, const int* in_sizes, int n_in,
                              void* d_out, int out_size)
{
    (void)in_sizes; (void)n_in; (void)out_size;
    const float* x      = (const float*)d_in[0];
    const float* w_qkv  = (const float*)d_in[1];
    const float* w_proj = (const float*)d_in[2];
    const float* b_proj = (const float*)d_in[3];
    const float* ln1_g  = (const float*)d_in[4];
    const float* ln1_b  = (const float*)d_in[5];
    const float* w1     = (const float*)d_in[6];
    const float* b1     = (const float*)d_in[7];
    const float* w2     = (const float*)d_in[8];
    const float* b2     = (const float*)d_in[9];
    const float* ln2_g  = (const float*)d_in[10];
    const float* ln2_b  = (const float*)d_in[11];
    float* out = (float*)d_out;

    __half *p_h, *p_qkv, *p_o, *p_ffn, *p_wq, *p_wp, *p_w1, *p_w2;
    float *p_x1;
    cudaGetSymbolAddress((void**)&p_h,   g_h);
    cudaGetSymbolAddress((void**)&p_qkv, g_qkv);
    cudaGetSymbolAddress((void**)&p_o,   g_o);
    cudaGetSymbolAddress((void**)&p_x1,  g_x1);
    cudaGetSymbolAddress((void**)&p_ffn, g_ffn);
    cudaGetSymbolAddress((void**)&p_wq,  g_wq);
    cudaGetSymbolAddress((void**)&p_wp,  g_wp);
    cudaGetSymbolAddress((void**)&p_w1,  g_w1t);
    cudaGetSymbolAddress((void**)&p_w2,  g_w2t);

    cudaFuncSetAttribute(gemm_f16<0,1>, cudaFuncAttributeMaxDynamicSharedMemorySize, GEMM_SMEM);
    cudaFuncSetAttribute(gemm_f16<1,0>, cudaFuncAttributeMaxDynamicSharedMemorySize, GEMM_SMEM);
    cudaFuncSetAttribute(gemm_f16<2,1>, cudaFuncAttributeMaxDynamicSharedMemorySize, GEMM_SMEM);

    cvt_transpose<<<dim3(3*DIMN/32, DIMN/32),   dim3(32,8)>>>(w_qkv,  p_wq, DIMN,   3*DIMN);
    cvt_transpose<<<dim3(DIMN/32,   DIMN/32),   dim3(32,8)>>>(w_proj, p_wp, DIMN,   DIMN);
    cvt_transpose<<<dim3(HIDDEN/32, DIMN/32),   dim3(32,8)>>>(w1,     p_w1, DIMN,   HIDDEN);
    cvt_transpose<<<dim3(DIMN/32,   HIDDEN/32), dim3(32,8)>>>(w2,     p_w2, HIDDEN, DIMN);

    ln_kernel<<<MROWS, 256>>>(x, ln1_g, ln1_b, p_h);
    gemm_f16<0,1><<<dim3(3*DIMN/128, MROWS/256), 512, GEMM_SMEM>>>(p_h, p_wq, nullptr, nullptr, p_qkv, DIMN, 3*DIMN);
    attn_f16<<<dim3(BB*NHEADS, SEQ/128), 256>>>(p_qkv, p_o);
    gemm_f16<1,0><<<dim3(DIMN/128, MROWS/256), 512, GEMM_SMEM>>>(p_o, p_wp, b_proj, x, p_x1, DIMN, DIMN);
    ln_kernel<<<MROWS, 256>>>(p_x1, ln2_g, ln2_b, p_h);
    gemm_f16<2,1><<<dim3(HIDDEN/128, MROWS/256), 512, GEMM_SMEM>>>(p_h, p_w1, b1, nullptr, p_ffn, DIMN, HIDDEN);
    gemm_f16<1,0><<<dim3(DIMN/128, MROWS/256), 512, GEMM_SMEM>>>(p_ffn, p_w2, b2, p_x1, out, HIDDEN, DIMN);
}